// round 5
// baseline (speedup 1.0000x reference)
#include <cuda_runtime.h>
#include <math.h>
#include <stdint.h>

// Problem constants
#define BATCH 512
#define HID   512
#define WDIM  1024
#define VOCAB 4004
#define TSTEPS 27
#define SLEN  80
#define NGATE 2048          // 4*HID
#define LSTM_IN 1536        // WDIM + HID

typedef unsigned long long ull;

// ---------------- scratch (device globals; allocation-free) ----------------
__device__ float g_a2[HID];
__device__ float g_a1[HID];
__device__ float g_a0e[HID];
__device__ float g_ctx[BATCH * HID];
__device__ float g_hbuf[2][BATCH * HID];
__device__ float g_c[BATCH * HID];
__device__ float g_Gbase[BATCH * NGATE];      // permuted cols: ctx @ W_ih_ctx^T + b_ih + b_hh
__device__ float g_Eproj[VOCAB * NGATE];      // permuted cols: embedding @ W_ih_word^T
__device__ ull   g_tokpack[2][BATCH];

// ---------------- small helpers ----------------
__device__ __forceinline__ ull ffma2(ull a, ull b, ull c) {
    ull d;
    asm("fma.rn.f32x2 %0, %1, %2, %3;" : "=l"(d) : "l"(a), "l"(b), "l"(c));
    return d;
}
__device__ __forceinline__ float2 unpack2(ull v) {
    float2 r;
    asm("mov.b64 {%0, %1}, %2;" : "=f"(r.x), "=f"(r.y) : "l"(v));
    return r;
}
__device__ __forceinline__ unsigned f2ord(float x) {
    unsigned u = __float_as_uint(x);
    return (u & 0x80000000u) ? ~u : (u | 0x80000000u);
}
__device__ __forceinline__ int decode_tok(ull p) {
    return (int)(0xFFFFFFFFu - (unsigned)(p & 0xFFFFFFFFull));
}
__device__ __forceinline__ float sigmoidf_(float x) {
    return 1.0f / (1.0f + expf(-x));
}
// gate-interleaved permutation: col n = unit*4+gate  ->  original row gate*512+unit
__device__ __forceinline__ int permrow(int n) {
    return ((n & 3) << 9) | (n >> 2);
}

#define CP_ASYNC16(dst, src, sz) \
    asm volatile("cp.async.cg.shared.global [%0], [%1], 16, %2;\n" \
                 :: "r"(dst), "l"(src), "r"(sz))
#define CP_COMMIT() asm volatile("cp.async.commit_group;\n")
#define CP_WAIT1()  asm volatile("cp.async.wait_group 1;\n")
#define CP_WAIT0()  asm volatile("cp.async.wait_group 0;\n")

// ---------------- init h, c, tokpack ----------------
__global__ void init_hc_kernel(const float* __restrict__ h0) {
    int b = blockIdx.x, u = threadIdx.x;
    g_hbuf[0][b * HID + u] = h0[b * HID + u];
    g_c[b * HID + u] = 0.0f;
    if (u == 0) { g_tokpack[0][b] = 0ull; g_tokpack[1][b] = 0ull; }
}

// ---------------- a-chain mat-vecs: out[j] = sum_h M[h,j] * vin[h] ----------
__global__ void matvecT_kernel(const float* __restrict__ Mt, int ld,
                               const float* __restrict__ vin_ext, int stage) {
    __shared__ float red[256];
    int j = blockIdx.x;
    const float* vin = (stage == 0) ? vin_ext : (stage == 1 ? g_a2 : g_a1);
    float acc = 0.0f;
    for (int h = threadIdx.x; h < HID; h += 256)
        acc += Mt[(size_t)h * ld + j] * vin[h];
    red[threadIdx.x] = acc;
    __syncthreads();
    for (int s = 128; s > 0; s >>= 1) {
        if (threadIdx.x < s) red[threadIdx.x] += red[threadIdx.x + s];
        __syncthreads();
    }
    if (threadIdx.x == 0) {
        float r = red[0];
        if (stage == 0)      g_a2[j]  = r;
        else if (stage == 1) g_a1[j]  = r;
        else                 g_a0e[j] = r;
    }
}

// ---------------- attention softmax + context (step-invariant) --------------
__global__ void attn_ctx_kernel(const float* __restrict__ enc) {
    __shared__ float sa[HID];
    __shared__ float sE[SLEN];
    __shared__ float sW[SLEN];
    int b = blockIdx.x;
    int tid = threadIdx.x;

    sa[tid]       = g_a0e[tid];
    sa[tid + 256] = g_a0e[tid + 256];
    __syncthreads();

    int w = tid >> 5, lane = tid & 31;
    for (int s = w; s < SLEN; s += 8) {
        const float* row = enc + ((size_t)b * SLEN + s) * HID;
        float acc = 0.0f;
        for (int k = lane; k < HID; k += 32) acc += row[k] * sa[k];
        #pragma unroll
        for (int off = 16; off > 0; off >>= 1)
            acc += __shfl_xor_sync(0xffffffffu, acc, off);
        if (lane == 0) sE[s] = acc;
    }
    __syncthreads();

    if (tid < 32) {
        float v0 = (tid      < SLEN) ? sE[tid]      : -INFINITY;
        float v1 = (tid + 32 < SLEN) ? sE[tid + 32] : -INFINITY;
        float v2 = (tid + 64 < SLEN) ? sE[tid + 64] : -INFINITY;
        float m = fmaxf(v0, fmaxf(v1, v2));
        #pragma unroll
        for (int off = 16; off > 0; off >>= 1)
            m = fmaxf(m, __shfl_xor_sync(0xffffffffu, m, off));
        float e0 = (tid      < SLEN) ? expf(v0 - m) : 0.0f;
        float e1 = (tid + 32 < SLEN) ? expf(v1 - m) : 0.0f;
        float e2 = (tid + 64 < SLEN) ? expf(v2 - m) : 0.0f;
        float s = e0 + e1 + e2;
        #pragma unroll
        for (int off = 16; off > 0; off >>= 1)
            s += __shfl_xor_sync(0xffffffffu, s, off);
        if (tid      < SLEN) sW[tid]      = e0 / s;
        if (tid + 32 < SLEN) sW[tid + 32] = e1 / s;
        if (tid + 64 < SLEN) sW[tid + 64] = e2 / s;
    }
    __syncthreads();

    for (int h = tid; h < HID; h += 256) {
        float acc = 0.0f;
        for (int s = 0; s < SLEN; s++)
            acc += sW[s] * enc[((size_t)b * SLEN + s) * HID + h];
        g_ctx[b * HID + h] = acc;
    }
}

// ---------------- K-packed fp32x2 GEMM, BM=64 BN=64 BK=32, 128 thr, 4x8 ----
// C[m,n] = sum_k A[m,k]*B[n,k]; f32x2 lanes carry (even-k, odd-k) partials.
// cp.async 2-stage pipeline; XOR-swizzled K-contiguous smem tiles.
// MODE 0: Gbase  = ctx @ W_ih_ctx^T (B rows permuted; +b_ih+b_hh permuted)
// MODE 1: gates  = h @ W_hh^T (perm) + Gbase + Eproj[tok]; fused LSTM -> h,c
// MODE 2: logits = h @ out_w^T + out_b; store seq + fused argmax
// MODE 3: Eproj  = emb @ W_ih_word^T (B rows permuted)
template <int MODE>
__global__ __launch_bounds__(128, 4)
void gemm_kernel(const float* __restrict__ Ap,
                 const float* __restrict__ Bp, int ldb,
                 float* __restrict__ Cp,
                 int M, int N, int K,
                 const float* __restrict__ bias1,
                 const float* __restrict__ bias2,
                 int t, float* __restrict__ pred) {
    __shared__ __align__(16) float As[2][64 * 32];
    __shared__ __align__(16) float Bs[2][64 * 32];
    __shared__ int s_tok[64];

    const int tid = threadIdx.x;
    const int bm = blockIdx.y * 64;
    const int bn = blockIdx.x * 64;
    const int tm = tid >> 3;   // 0..15 -> rows tm*4..tm*4+3
    const int tn = tid & 7;    // 0..7  -> cols tn*8..tn*8+7

    const float* A;
    int lda;
    if (MODE == 3)      { A = Ap;    lda = WDIM; }
    else if (MODE == 0) { A = g_ctx; lda = HID; }
    else                { A = g_hbuf[(MODE == 1) ? (t & 1) : ((t + 1) & 1)]; lda = HID; }

    if (MODE == 1 && tid < 64)
        s_tok[tid] = (t == 0) ? 1 : decode_tok(g_tokpack[(t - 1) & 1][bm + tid]);
    if (MODE == 2 && blockIdx.x == 0 && tid < 64)
        g_tokpack[(t + 1) & 1][bm + tid] = 0ull;   // prep buffer for next step

    const uint32_t sA = (uint32_t)__cvta_generic_to_shared(&As[0][0]);
    const uint32_t sB = (uint32_t)__cvta_generic_to_shared(&Bs[0][0]);

    // per-thread loader geometry: row = tid>>1 (0..63), chunk base = (tid&1)*4
    const int ldrow = tid >> 1;
    const int ldcb  = (tid & 1) * 4;
    const int aswz  = (ldrow >> 2) & 7;
    const int bswz  = (ldrow >> 3) & 7;

    // A source row (MODE 3 may be out of range)
    int agr = bm + ldrow;
    int a_sz = 16;
    if (MODE == 3 && agr >= M) { a_sz = 0; agr = 0; }
    const float* a_srcbase = A + (size_t)agr * lda + ldcb * 4;

    // B source row
    int bgr = bn + ldrow;
    int b_sz = 16;
    int brow;
    if (MODE == 2) {
        if (bgr >= N) { b_sz = 0; brow = 0; } else brow = bgr;
    } else {
        brow = permrow(bgr);
    }
    const float* b_srcbase = Bp + (size_t)brow * ldb + ldcb * 4;

    const uint32_t a_dst = sA + ldrow * 128;
    const uint32_t b_dst = sB + ldrow * 128;

    ull acc[4][8];
    #pragma unroll
    for (int i = 0; i < 4; i++)
        #pragma unroll
        for (int j = 0; j < 8; j++) acc[i][j] = 0ull;

    const int nch = K >> 5;

    // prologue: stage 0
    {
        #pragma unroll
        for (int jj = 0; jj < 4; jj++) {
            int c = ldcb + jj;
            CP_ASYNC16(a_dst + (((c ^ aswz)) << 4), a_srcbase + jj * 4, a_sz);
            CP_ASYNC16(b_dst + (((c ^ bswz)) << 4), b_srcbase + jj * 4, b_sz);
        }
        CP_COMMIT();
    }

    for (int ch = 0; ch < nch; ch++) {
        if (ch + 1 < nch) {
            int k0 = (ch + 1) << 5;
            uint32_t soff = ((ch + 1) & 1) ? 8192u : 0u;
            #pragma unroll
            for (int jj = 0; jj < 4; jj++) {
                int c = ldcb + jj;
                CP_ASYNC16(a_dst + soff + ((c ^ aswz) << 4), a_srcbase + k0 + jj * 4, a_sz);
                CP_ASYNC16(b_dst + soff + ((c ^ bswz) << 4), b_srcbase + k0 + jj * 4, b_sz);
            }
            CP_COMMIT();
            CP_WAIT1();
        } else {
            CP_WAIT0();
        }
        __syncthreads();

        const float* as = As[ch & 1];
        const float* bs = Bs[ch & 1];
        #pragma unroll
        for (int c = 0; c < 8; c++) {
            const int aoff = (c ^ (tm & 7)) << 2;
            const int boff = (c ^ tn) << 2;
            ulonglong2 av0 = *(const ulonglong2*)&as[(tm * 4 + 0) * 32 + aoff];
            ulonglong2 av1 = *(const ulonglong2*)&as[(tm * 4 + 1) * 32 + aoff];
            ulonglong2 av2 = *(const ulonglong2*)&as[(tm * 4 + 2) * 32 + aoff];
            ulonglong2 av3 = *(const ulonglong2*)&as[(tm * 4 + 3) * 32 + aoff];
            #pragma unroll
            for (int j = 0; j < 8; j++) {
                ulonglong2 bv = *(const ulonglong2*)&bs[(tn * 8 + j) * 32 + boff];
                acc[0][j] = ffma2(av0.x, bv.x, acc[0][j]);
                acc[0][j] = ffma2(av0.y, bv.y, acc[0][j]);
                acc[1][j] = ffma2(av1.x, bv.x, acc[1][j]);
                acc[1][j] = ffma2(av1.y, bv.y, acc[1][j]);
                acc[2][j] = ffma2(av2.x, bv.x, acc[2][j]);
                acc[2][j] = ffma2(av2.y, bv.y, acc[2][j]);
                acc[3][j] = ffma2(av3.x, bv.x, acc[3][j]);
                acc[3][j] = ffma2(av3.y, bv.y, acc[3][j]);
            }
        }
        __syncthreads();
    }

    // lane-sum: cv[i][j] = even-k partial + odd-k partial
    float cv[4][8];
    #pragma unroll
    for (int i = 0; i < 4; i++)
        #pragma unroll
        for (int j = 0; j < 8; j++) {
            float2 p = unpack2(acc[i][j]);
            cv[i][j] = p.x + p.y;
        }

    const int ncol = bn + tn * 8;

    if (MODE == 0 || MODE == 3) {
        float badd[8];
        #pragma unroll
        for (int j = 0; j < 8; j++) {
            if (MODE == 0) {
                int pr = permrow(ncol + j);
                badd[j] = bias1[pr] + bias2[pr];
            } else badd[j] = 0.0f;
        }
        float* Cb = (MODE == 0) ? g_Gbase : g_Eproj;
        #pragma unroll
        for (int i = 0; i < 4; i++) {
            int m = bm + tm * 4 + i;
            if (MODE == 3 && m >= M) continue;
            float4 v0 = make_float4(cv[i][0] + badd[0], cv[i][1] + badd[1],
                                    cv[i][2] + badd[2], cv[i][3] + badd[3]);
            float4 v1 = make_float4(cv[i][4] + badd[4], cv[i][5] + badd[5],
                                    cv[i][6] + badd[6], cv[i][7] + badd[7]);
            *reinterpret_cast<float4*>(Cb + (size_t)m * NGATE + ncol)     = v0;
            *reinterpret_cast<float4*>(Cb + (size_t)m * NGATE + ncol + 4) = v1;
        }
    } else if (MODE == 1) {
        // fused LSTM: cols = two (i,f,g,o) quadruples for units u0, u0+1
        const int u0 = ncol >> 2;
        float* hW = g_hbuf[(t + 1) & 1];
        #pragma unroll
        for (int i = 0; i < 4; i++) {
            int m = bm + tm * 4 + i;
            int tok = s_tok[tm * 4 + i];
            float4 gb0 = *reinterpret_cast<const float4*>(g_Gbase + (size_t)m * NGATE + ncol);
            float4 gb1 = *reinterpret_cast<const float4*>(g_Gbase + (size_t)m * NGATE + ncol + 4);
            float4 ep0 = *reinterpret_cast<const float4*>(g_Eproj + (size_t)tok * NGATE + ncol);
            float4 ep1 = *reinterpret_cast<const float4*>(g_Eproj + (size_t)tok * NGATE + ncol + 4);
            {
                float gi = cv[i][0] + gb0.x + ep0.x;
                float gf = cv[i][1] + gb0.y + ep0.y;
                float gg = cv[i][2] + gb0.z + ep0.z;
                float go = cv[i][3] + gb0.w + ep0.w;
                float c_old = g_c[m * HID + u0];
                float cn = sigmoidf_(gf) * c_old + sigmoidf_(gi) * tanhf(gg);
                g_c[m * HID + u0] = cn;
                hW[m * HID + u0] = sigmoidf_(go) * tanhf(cn);
            }
            {
                float gi = cv[i][4] + gb1.x + ep1.x;
                float gf = cv[i][5] + gb1.y + ep1.y;
                float gg = cv[i][6] + gb1.z + ep1.z;
                float go = cv[i][7] + gb1.w + ep1.w;
                float c_old = g_c[m * HID + u0 + 1];
                float cn = sigmoidf_(gf) * c_old + sigmoidf_(gi) * tanhf(gg);
                g_c[m * HID + u0 + 1] = cn;
                hW[m * HID + u0 + 1] = sigmoidf_(go) * tanhf(cn);
            }
            if (blockIdx.x == 0 && tn == 0 && t > 0 && pred)
                pred[m * TSTEPS + (t - 1)] = (float)tok;
        }
    } else {  // MODE 2: logits + argmax
        #pragma unroll
        for (int i = 0; i < 4; i++) {
            int m = bm + tm * 4 + i;
            float v[8];
            ull best = 0ull;
            #pragma unroll
            for (int j = 0; j < 8; j++) {
                int n = ncol + j;
                v[j] = cv[i][j] + ((n < N) ? bias1[n] : 0.0f);
                if (n < N) {
                    ull cand = ((ull)f2ord(v[j]) << 32) | (ull)(0xFFFFFFFFu - (unsigned)n);
                    if (cand > best) best = cand;
                }
            }
            if (Cp) {
                float* orow = Cp + (size_t)m * (TSTEPS * VOCAB) + (size_t)t * VOCAB;
                if (ncol + 7 < N) {
                    *reinterpret_cast<float4*>(orow + ncol)     = make_float4(v[0], v[1], v[2], v[3]);
                    *reinterpret_cast<float4*>(orow + ncol + 4) = make_float4(v[4], v[5], v[6], v[7]);
                } else {
                    #pragma unroll
                    for (int j = 0; j < 8; j++)
                        if (ncol + j < N) orow[ncol + j] = v[j];
                }
            }
            #pragma unroll
            for (int off = 4; off > 0; off >>= 1) {
                ull o = __shfl_xor_sync(0xffffffffu, best, off, 8);
                if (o > best) best = o;
            }
            if (tn == 0) atomicMax(&g_tokpack[t & 1][m], best);
        }
    }
}

// ---------------- final pred ----------------
__global__ void final_pred_kernel(float* __restrict__ pred) {
    int b = threadIdx.x;
    pred[b * TSTEPS + (TSTEPS - 1)] = (float)decode_tok(g_tokpack[(TSTEPS - 1) & 1][b]);
}

// ---------------- launch ----------------
extern "C" void kernel_launch(void* const* d_in, const int* in_sizes, int n_in,
                              void* d_out, int out_size) {
    const float* enc_last = (const float*)d_in[0];   // [1,512,512]
    const float* enc_out  = (const float*)d_in[1];   // [512,80,512]
    const float* emb      = (const float*)d_in[2];   // [4004,1024]
    const float* w1       = (const float*)d_in[3];   // [512,1024]
    const float* w2       = (const float*)d_in[5];   // [512,512]
    const float* w3       = (const float*)d_in[7];   // [512,512]
    const float* wv       = (const float*)d_in[9];   // [1,512]
    const float* w_ih     = (const float*)d_in[10];  // [2048,1536]
    const float* w_hh     = (const float*)d_in[11];  // [2048,512]
    const float* b_ih     = (const float*)d_in[12];  // [2048]
    const float* b_hh     = (const float*)d_in[13];  // [2048]
    const float* out_w    = (const float*)d_in[14];  // [4004,512]
    const float* out_b    = (const float*)d_in[15];  // [4004]

    float* out = (float*)d_out;
    const long long SEQ  = (long long)BATCH * TSTEPS * VOCAB;
    const long long PRED = (long long)BATCH * TSTEPS;
    float* seq_ptr  = ((long long)out_size >= SEQ) ? out : nullptr;
    float* pred_ptr = ((long long)out_size >= SEQ + PRED) ? (out + SEQ) : nullptr;

    // --- precompute
    init_hc_kernel<<<BATCH, HID>>>(enc_last);
    matvecT_kernel<<<HID, 256>>>(w3, HID, wv, 0);       // a2 = W3^T wv
    matvecT_kernel<<<HID, 256>>>(w2, HID, nullptr, 1);  // a1 = W2^T a2
    matvecT_kernel<<<HID, 256>>>(w1, WDIM, nullptr, 2); // a0e = (W1^T a1)[:512]
    attn_ctx_kernel<<<BATCH, 256>>>(enc_out);

    // G_base (permuted cols) = ctx @ W_ih_ctx^T + b_ih + b_hh
    gemm_kernel<0><<<dim3(NGATE / 64, BATCH / 64), 128>>>(
        nullptr, w_ih + WDIM, LSTM_IN, nullptr,
        BATCH, NGATE, HID, b_ih, b_hh, 0, nullptr);

    // E_proj (permuted cols) = embedding @ W_ih_word^T
    gemm_kernel<3><<<dim3(NGATE / 64, (VOCAB + 63) / 64), 128>>>(
        emb, w_ih, LSTM_IN, nullptr,
        VOCAB, NGATE, WDIM, nullptr, nullptr, 0, nullptr);

    // --- 27 sequential decode steps (2 launches each)
    for (int t = 0; t < TSTEPS; t++) {
        // gates + fused LSTM -> h_new, c ; also writes pred[t-1]
        gemm_kernel<1><<<dim3(NGATE / 64, BATCH / 64), 128>>>(
            nullptr, w_hh, HID, nullptr,
            BATCH, NGATE, HID, nullptr, nullptr, t, pred_ptr);
        // logits + bias + store + fused argmax
        gemm_kernel<2><<<dim3((VOCAB + 63) / 64, BATCH / 64), 128>>>(
            nullptr, out_w, HID, seq_ptr,
            BATCH, VOCAB, HID, out_b, nullptr, t, nullptr);
    }
    if (pred_ptr)
        final_pred_kernel<<<1, BATCH>>>(pred_ptr);
}

// round 9
// speedup vs baseline: 1.1113x; 1.1113x over previous
#include <cuda_runtime.h>
#include <cuda_bf16.h>
#include <math.h>
#include <stdint.h>

#define BATCH 512
#define HID   512
#define WDIM  1024
#define VOCAB 4004
#define VPAD  4096
#define TSTEPS 27
#define SLEN  80
#define NGATE 2048
#define LSTM_IN 1536

typedef unsigned long long ull;

// ---------------- device scratch ----------------
__device__ float g_a2[HID];
__device__ float g_a1[HID];
__device__ float g_a0e[HID];
__device__ float g_ctx[BATCH * HID];
__device__ float g_c[BATCH * HID];
__device__ float g_Gbase[BATCH * NGATE];      // permuted cols
__device__ float g_Eproj[VOCAB * NGATE];      // permuted cols
__device__ ull   g_tokpack[2][BATCH];
__device__ __align__(16) __nv_bfloat16 g_h3[2][3][BATCH * HID];
__device__ __align__(16) __nv_bfloat16 g_Whh3[3][NGATE * HID];  // rows gate-permuted
__device__ __align__(16) __nv_bfloat16 g_Wout3[3][VPAD * HID];  // rows >= VOCAB zero

// ---------------- helpers ----------------
__device__ __forceinline__ ull ffma2(ull a, ull b, ull c) {
    ull d;
    asm("fma.rn.f32x2 %0, %1, %2, %3;" : "=l"(d) : "l"(a), "l"(b), "l"(c));
    return d;
}
__device__ __forceinline__ float2 unpack2(ull v) {
    float2 r;
    asm("mov.b64 {%0, %1}, %2;" : "=f"(r.x), "=f"(r.y) : "l"(v));
    return r;
}
__device__ __forceinline__ unsigned f2ord(float x) {
    unsigned u = __float_as_uint(x);
    return (u & 0x80000000u) ? ~u : (u | 0x80000000u);
}
__device__ __forceinline__ int decode_tok(ull p) {
    return (int)(0xFFFFFFFFu - (unsigned)(p & 0xFFFFFFFFull));
}
__device__ __forceinline__ float sigmoidf_(float x) { return 1.0f / (1.0f + expf(-x)); }
__device__ __forceinline__ int permrow(int n) { return ((n & 3) << 9) | (n >> 2); }
__device__ __forceinline__ void split3(float x, __nv_bfloat16& a, __nv_bfloat16& b,
                                       __nv_bfloat16& c) {
    a = __float2bfloat16(x);
    float r = x - __bfloat162float(a);
    b = __float2bfloat16(r);
    r -= __bfloat162float(b);
    c = __float2bfloat16(r);
}

#define CP_ASYNC16P(dst, src, sz) \
    asm volatile("cp.async.cg.shared.global [%0], [%1], 16, %2;\n" \
                 :: "r"(dst), "l"(src), "r"(sz))
#define CP_ASYNC16(dst, src) \
    asm volatile("cp.async.cg.shared.global [%0], [%1], 16;\n" :: "r"(dst), "l"(src))
#define CP_COMMIT() asm volatile("cp.async.commit_group;\n")
#define CP_WAIT1()  asm volatile("cp.async.wait_group 1;\n")
#define CP_WAIT0()  asm volatile("cp.async.wait_group 0;\n")

__device__ __forceinline__ void ldm_x4(uint32_t* r, uint32_t addr) {
    asm volatile("ldmatrix.sync.aligned.m8n8.x4.shared.b16 {%0,%1,%2,%3}, [%4];"
        : "=r"(r[0]), "=r"(r[1]), "=r"(r[2]), "=r"(r[3]) : "r"(addr));
}
__device__ __forceinline__ void mma16816(float* d, const uint32_t* a,
                                         uint32_t b0, uint32_t b1) {
    asm volatile("mma.sync.aligned.m16n8k16.row.col.f32.bf16.bf16.f32 "
        "{%0,%1,%2,%3}, {%4,%5,%6,%7}, {%8,%9}, {%0,%1,%2,%3};"
        : "+f"(d[0]), "+f"(d[1]), "+f"(d[2]), "+f"(d[3])
        : "r"(a[0]), "r"(a[1]), "r"(a[2]), "r"(a[3]), "r"(b0), "r"(b1));
}

// smem layout for mma kernels (dynamic)
// stage: A 3 splits x (128 rows x 80B) ; B 3 splits x (64 rows x 80B)
#define STG_SZ   46080u
#define AOFF(st, s) ((uint32_t)((st) * STG_SZ + (s) * 10240u))
#define BOFF(st, s) ((uint32_t)((st) * STG_SZ + 30720u + (s) * 5120u))
#define SB_BIAS  92160u
#define SB_TOK   92416u
#define MM_SMEM  92928u

// ---------------- init ----------------
__global__ void init_hc_kernel(const float* __restrict__ h0) {
    int b = blockIdx.x, u = threadIdx.x;
    float x = h0[b * HID + u];
    __nv_bfloat16 s0, s1, s2;
    split3(x, s0, s1, s2);
    g_h3[0][0][b * HID + u] = s0;
    g_h3[0][1][b * HID + u] = s1;
    g_h3[0][2][b * HID + u] = s2;
    g_c[b * HID + u] = 0.0f;
    if (u == 0) { g_tokpack[0][b] = 0ull; g_tokpack[1][b] = 0ull; }
}

// which: 0 = Whh (perm rows), 1 = Wout (pad rows)
__global__ void split_kernel(const float* __restrict__ src, int which) {
    int r = blockIdx.x;
    for (int k = threadIdx.x; k < HID; k += 256) {
        float x;
        if (which == 0) x = src[(size_t)permrow(r) * HID + k];
        else            x = (r < VOCAB) ? src[(size_t)r * HID + k] : 0.0f;
        __nv_bfloat16 s0, s1, s2;
        split3(x, s0, s1, s2);
        size_t o = (size_t)r * HID + k;
        if (which == 0) { g_Whh3[0][o] = s0;  g_Whh3[1][o] = s1;  g_Whh3[2][o] = s2; }
        else            { g_Wout3[0][o] = s0; g_Wout3[1][o] = s1; g_Wout3[2][o] = s2; }
    }
}

// ---------------- a-chain mat-vecs ----------------
__global__ void matvecT_kernel(const float* __restrict__ Mt, int ld,
                               const float* __restrict__ vin_ext, int stage) {
    __shared__ float red[256];
    int j = blockIdx.x;
    const float* vin = (stage == 0) ? vin_ext : (stage == 1 ? g_a2 : g_a1);
    float acc = 0.0f;
    for (int h = threadIdx.x; h < HID; h += 256)
        acc += Mt[(size_t)h * ld + j] * vin[h];
    red[threadIdx.x] = acc;
    __syncthreads();
    for (int s = 128; s > 0; s >>= 1) {
        if (threadIdx.x < s) red[threadIdx.x] += red[threadIdx.x + s];
        __syncthreads();
    }
    if (threadIdx.x == 0) {
        float r = red[0];
        if (stage == 0)      g_a2[j]  = r;
        else if (stage == 1) g_a1[j]  = r;
        else                 g_a0e[j] = r;
    }
}

// ---------------- attention context (step-invariant) ----------------
__global__ void attn_ctx_kernel(const float* __restrict__ enc) {
    __shared__ float sa[HID];
    __shared__ float sE[SLEN];
    __shared__ float sW[SLEN];
    int b = blockIdx.x, tid = threadIdx.x;
    sa[tid] = g_a0e[tid];
    sa[tid + 256] = g_a0e[tid + 256];
    __syncthreads();
    int w = tid >> 5, lane = tid & 31;
    for (int s = w; s < SLEN; s += 8) {
        const float* row = enc + ((size_t)b * SLEN + s) * HID;
        float acc = 0.0f;
        for (int k = lane; k < HID; k += 32) acc += row[k] * sa[k];
        #pragma unroll
        for (int off = 16; off > 0; off >>= 1)
            acc += __shfl_xor_sync(0xffffffffu, acc, off);
        if (lane == 0) sE[s] = acc;
    }
    __syncthreads();
    if (tid < 32) {
        float v0 = (tid < SLEN) ? sE[tid] : -INFINITY;
        float v1 = (tid + 32 < SLEN) ? sE[tid + 32] : -INFINITY;
        float v2 = (tid + 64 < SLEN) ? sE[tid + 64] : -INFINITY;
        float m = fmaxf(v0, fmaxf(v1, v2));
        #pragma unroll
        for (int off = 16; off > 0; off >>= 1)
            m = fmaxf(m, __shfl_xor_sync(0xffffffffu, m, off));
        float e0 = (tid < SLEN) ? expf(v0 - m) : 0.0f;
        float e1 = (tid + 32 < SLEN) ? expf(v1 - m) : 0.0f;
        float e2 = (tid + 64 < SLEN) ? expf(v2 - m) : 0.0f;
        float s = e0 + e1 + e2;
        #pragma unroll
        for (int off = 16; off > 0; off >>= 1)
            s += __shfl_xor_sync(0xffffffffu, s, off);
        if (tid < SLEN)      sW[tid]      = e0 / s;
        if (tid + 32 < SLEN) sW[tid + 32] = e1 / s;
        if (tid + 64 < SLEN) sW[tid + 64] = e2 / s;
    }
    __syncthreads();
    for (int h = tid; h < HID; h += 256) {
        float acc = 0.0f;
        for (int s = 0; s < SLEN; s++)
            acc += sW[s] * enc[((size_t)b * SLEN + s) * HID + h];
        g_ctx[b * HID + h] = acc;
    }
}

// ---------------- FFMA2 precompute GEMM (R4-proven) -------------------------
// MODE 0: Gbase = ctx @ W_ih_ctx^T (B rows perm; + b_ih + b_hh perm)
// MODE 3: Eproj = emb @ W_ih_word^T (B rows perm)
template <int MODE>
__global__ __launch_bounds__(128, 4)
void pre_gemm(const float* __restrict__ Ap,
              const float* __restrict__ Bp, int ldb,
              int M, int K,
              const float* __restrict__ bias1, const float* __restrict__ bias2) {
    __shared__ __align__(16) float As[2][64 * 32];
    __shared__ __align__(16) float Bs[2][64 * 32];

    const int tid = threadIdx.x;
    const int bm = blockIdx.y * 64;
    const int bn = blockIdx.x * 64;
    const int tm = tid >> 3;
    const int tn = tid & 7;

    const float* A = (MODE == 3) ? Ap : g_ctx;
    const int lda = (MODE == 3) ? WDIM : HID;

    const uint32_t sA = (uint32_t)__cvta_generic_to_shared(&As[0][0]);
    const uint32_t sB = (uint32_t)__cvta_generic_to_shared(&Bs[0][0]);

    const int ldrow = tid >> 1;
    const int ldcb  = (tid & 1) * 4;
    const int aswz  = (ldrow >> 2) & 7;
    const int bswz  = (ldrow >> 3) & 7;

    int agr = bm + ldrow;
    int a_sz = 16;
    if (MODE == 3 && agr >= M) { a_sz = 0; agr = 0; }
    const float* a_srcbase = A + (size_t)agr * lda + ldcb * 4;
    const float* b_srcbase = Bp + (size_t)permrow(bn + ldrow) * ldb + ldcb * 4;

    const uint32_t a_dst = sA + ldrow * 128;
    const uint32_t b_dst = sB + ldrow * 128;

    ull acc[4][8];
    #pragma unroll
    for (int i = 0; i < 4; i++)
        #pragma unroll
        for (int j = 0; j < 8; j++) acc[i][j] = 0ull;

    const int nch = K >> 5;
    {
        #pragma unroll
        for (int jj = 0; jj < 4; jj++) {
            int c = ldcb + jj;
            CP_ASYNC16P(a_dst + ((c ^ aswz) << 4), a_srcbase + jj * 4, a_sz);
            CP_ASYNC16(b_dst + ((c ^ bswz) << 4), b_srcbase + jj * 4);
        }
        CP_COMMIT();
    }
    for (int ch = 0; ch < nch; ch++) {
        if (ch + 1 < nch) {
            int k0 = (ch + 1) << 5;
            uint32_t soff = ((ch + 1) & 1) ? 8192u : 0u;
            #pragma unroll
            for (int jj = 0; jj < 4; jj++) {
                int c = ldcb + jj;
                CP_ASYNC16P(a_dst + soff + ((c ^ aswz) << 4), a_srcbase + k0 + jj * 4, a_sz);
                CP_ASYNC16(b_dst + soff + ((c ^ bswz) << 4), b_srcbase + k0 + jj * 4);
            }
            CP_COMMIT();
            CP_WAIT1();
        } else {
            CP_WAIT0();
        }
        __syncthreads();

        const float* as = As[ch & 1];
        const float* bs = Bs[ch & 1];
        #pragma unroll
        for (int c = 0; c < 8; c++) {
            const int aoff = (c ^ (tm & 7)) << 2;
            const int boff = (c ^ tn) << 2;
            ulonglong2 av0 = *(const ulonglong2*)&as[(tm * 4 + 0) * 32 + aoff];
            ulonglong2 av1 = *(const ulonglong2*)&as[(tm * 4 + 1) * 32 + aoff];
            ulonglong2 av2 = *(const ulonglong2*)&as[(tm * 4 + 2) * 32 + aoff];
            ulonglong2 av3 = *(const ulonglong2*)&as[(tm * 4 + 3) * 32 + aoff];
            #pragma unroll
            for (int j = 0; j < 8; j++) {
                ulonglong2 bv = *(const ulonglong2*)&bs[(tn * 8 + j) * 32 + boff];
                acc[0][j] = ffma2(av0.x, bv.x, acc[0][j]);
                acc[0][j] = ffma2(av0.y, bv.y, acc[0][j]);
                acc[1][j] = ffma2(av1.x, bv.x, acc[1][j]);
                acc[1][j] = ffma2(av1.y, bv.y, acc[1][j]);
                acc[2][j] = ffma2(av2.x, bv.x, acc[2][j]);
                acc[2][j] = ffma2(av2.y, bv.y, acc[2][j]);
                acc[3][j] = ffma2(av3.x, bv.x, acc[3][j]);
                acc[3][j] = ffma2(av3.y, bv.y, acc[3][j]);
            }
        }
        __syncthreads();
    }

    const int ncol = bn + tn * 8;
    float badd[8];
    #pragma unroll
    for (int j = 0; j < 8; j++) {
        if (MODE == 0) {
            int pr = permrow(ncol + j);
            badd[j] = bias1[pr] + bias2[pr];
        } else badd[j] = 0.0f;
    }
    float* Cb = (MODE == 0) ? g_Gbase : g_Eproj;
    #pragma unroll
    for (int i = 0; i < 4; i++) {
        int m = bm + tm * 4 + i;
        if (MODE == 3 && m >= M) continue;
        float2 p0, p1, p2, p3;
        p0 = unpack2(acc[i][0]); p1 = unpack2(acc[i][1]);
        p2 = unpack2(acc[i][2]); p3 = unpack2(acc[i][3]);
        float4 v0 = make_float4(p0.x + p0.y + badd[0], p1.x + p1.y + badd[1],
                                p2.x + p2.y + badd[2], p3.x + p3.y + badd[3]);
        p0 = unpack2(acc[i][4]); p1 = unpack2(acc[i][5]);
        p2 = unpack2(acc[i][6]); p3 = unpack2(acc[i][7]);
        float4 v1 = make_float4(p0.x + p0.y + badd[4], p1.x + p1.y + badd[5],
                                p2.x + p2.y + badd[6], p3.x + p3.y + badd[7]);
        *reinterpret_cast<float4*>(Cb + (size_t)m * NGATE + ncol)     = v0;
        *reinterpret_cast<float4*>(Cb + (size_t)m * NGATE + ncol + 4) = v1;
    }
}

// ---------------- mma.sync 3-split GEMM (decode loop), 128x64 tile ---------
// MODE 1: gates = h[t] @ Whh^T + Gbase + Eproj[tok]; fused LSTM -> h[t+1], c
// MODE 2: logits = h[t+1] @ Wout^T + out_b; seq store + argmax
template <int MODE>
__global__ __launch_bounds__(256)
void mma_gemm(int t, const float* __restrict__ bias1,
              float* __restrict__ seq, float* __restrict__ pred) {
    extern __shared__ __align__(16) char smem[];
    const uint32_t sbase = (uint32_t)__cvta_generic_to_shared(smem);

    const int tid = threadIdx.x;
    const int wid = tid >> 5;
    const int lane = tid & 31;
    const int bm = blockIdx.y * 128;
    const int bn = blockIdx.x * 64;
    const int wm = (wid & 3) * 32;
    const int wn = (wid >> 2) * 32;

    const int hb = (MODE == 1) ? (t & 1) : ((t + 1) & 1);
    const __nv_bfloat16* Aps[3] = {g_h3[hb][0], g_h3[hb][1], g_h3[hb][2]};
    const __nv_bfloat16* Bps[3] = {
        (MODE == 1) ? g_Whh3[0] : g_Wout3[0],
        (MODE == 1) ? g_Whh3[1] : g_Wout3[1],
        (MODE == 1) ? g_Whh3[2] : g_Wout3[2]};

    int* stok = (int*)(smem + SB_TOK);
    float* sbias = (float*)(smem + SB_BIAS);
    if (MODE == 1 && tid < 128)
        stok[tid] = (t == 0) ? 1 : decode_tok(g_tokpack[(t - 1) & 1][bm + tid]);
    if (MODE == 2) {
        if (blockIdx.x == 0 && tid < 128) g_tokpack[(t + 1) & 1][bm + tid] = 0ull;
        if (tid < 64) {
            int n = bn + tid;
            sbias[tid] = (n < VOCAB) ? bias1[n] : -3e38f;
        }
    }

    float acc[2][4][4];
    #pragma unroll
    for (int i = 0; i < 2; i++)
        #pragma unroll
        for (int j = 0; j < 4; j++)
            #pragma unroll
            for (int k = 0; k < 4; k++) acc[i][j][k] = 0.0f;

    // chunk loader: BK=32, 2304 16B-chunks / 256 threads = 9 each
    auto load_chunk = [&](int ch, int st) {
        const int k0 = ch << 5;
        #pragma unroll
        for (int i = 0; i < 9; i++) {
            int idx = i * 256 + tid;
            uint32_t dst;
            const __nv_bfloat16* src;
            if (idx < 1536) {
                int s = idx >> 9, rem = idx & 511, r = rem >> 2, c = rem & 3;
                dst = sbase + AOFF(st, s) + r * 80 + c * 16;
                src = Aps[s] + (size_t)(bm + r) * HID + k0 + c * 8;
            } else {
                int j = idx - 1536;
                int s = j >> 8, rem = j & 255, r = rem >> 2, c = rem & 3;
                dst = sbase + BOFF(st, s) + r * 80 + c * 16;
                src = Bps[s] + (size_t)(bn + r) * HID + k0 + c * 8;
            }
            CP_ASYNC16(dst, src);
        }
        CP_COMMIT();
    };

    const int nch = HID >> 5;   // 16
    load_chunk(0, 0);
    for (int ch = 0; ch < nch; ch++) {
        if (ch + 1 < nch) { load_chunk(ch + 1, (ch + 1) & 1); CP_WAIT1(); }
        else              { CP_WAIT0(); }
        __syncthreads();

        const int st = ch & 1;
        #pragma unroll
        for (int ks = 0; ks < 2; ks++) {
            uint32_t af[3][2][4], bf[3][2][4];
            #pragma unroll
            for (int s = 0; s < 3; s++) {
                #pragma unroll
                for (int mt = 0; mt < 2; mt++)
                    ldm_x4(af[s][mt], sbase + AOFF(st, s) +
                           (wm + mt * 16 + (lane & 15)) * 80 + ks * 32 +
                           ((lane >> 4) << 4));
                #pragma unroll
                for (int g = 0; g < 2; g++)
                    ldm_x4(bf[s][g], sbase + BOFF(st, s) +
                           (wn + g * 16 + (lane & 15)) * 80 + ks * 32 +
                           ((lane >> 4) << 4));
            }
            const int PA[6] = {0, 0, 1, 1, 2, 0};
            const int PB[6] = {0, 1, 0, 1, 0, 2};
            #pragma unroll
            for (int p = 0; p < 6; p++) {
                #pragma unroll
                for (int mt = 0; mt < 2; mt++)
                    #pragma unroll
                    for (int nt = 0; nt < 4; nt++) {
                        int g = nt >> 1, h = nt & 1;
                        mma16816(acc[mt][nt], af[PA[p]][mt],
                                 bf[PB[p]][g][h], bf[PB[p]][g][h + 2]);
                    }
            }
        }
        __syncthreads();
    }

    // accumulators -> smem tile [128][68] f32 (reuses stage buffers)
    float* ep = (float*)smem;
    #pragma unroll
    for (int mt = 0; mt < 2; mt++)
        #pragma unroll
        for (int nt = 0; nt < 4; nt++) {
            int row = wm + mt * 16 + (lane >> 2);
            int col = wn + nt * 8 + (lane & 3) * 2;
            float b0 = 0.0f, b1 = 0.0f;
            if (MODE == 2) { b0 = sbias[col]; b1 = sbias[col + 1]; }
            ep[row * 68 + col]           = acc[mt][nt][0] + b0;
            ep[row * 68 + col + 1]       = acc[mt][nt][1] + b1;
            ep[(row + 8) * 68 + col]     = acc[mt][nt][2] + b0;
            ep[(row + 8) * 68 + col + 1] = acc[mt][nt][3] + b1;
        }
    __syncthreads();

    const int m = tid >> 1;
    const int mg = bm + m;
    if (MODE == 1) {
        const int tok = stok[m];
        const int uo = (tid & 1) * 8;
        const int ho = (t + 1) & 1;
        #pragma unroll
        for (int j = 0; j < 8; j++) {
            int col = (uo + j) * 4;
            int gcol = bn + col;
            int u = gcol >> 2;
            float4 gb = *(const float4*)&g_Gbase[(size_t)mg * NGATE + gcol];
            float4 epj = *(const float4*)&g_Eproj[(size_t)tok * NGATE + gcol];
            float gi = ep[m * 68 + col]     + gb.x + epj.x;
            float gf = ep[m * 68 + col + 1] + gb.y + epj.y;
            float gg = ep[m * 68 + col + 2] + gb.z + epj.z;
            float go = ep[m * 68 + col + 3] + gb.w + epj.w;
            float cn = sigmoidf_(gf) * g_c[mg * HID + u] + sigmoidf_(gi) * tanhf(gg);
            g_c[mg * HID + u] = cn;
            float hn = sigmoidf_(go) * tanhf(cn);
            __nv_bfloat16 s0, s1, s2;
            split3(hn, s0, s1, s2);
            g_h3[ho][0][mg * HID + u] = s0;
            g_h3[ho][1][mg * HID + u] = s1;
            g_h3[ho][2][mg * HID + u] = s2;
        }
        if (blockIdx.x == 0 && (tid & 1) == 0 && t > 0 && pred)
            pred[mg * TSTEPS + (t - 1)] = (float)tok;
    } else {
        const int cs = (tid & 1) * 32;
        ull best = 0ull;
        #pragma unroll
        for (int k = 0; k < 32; k++) {
            float v = ep[m * 68 + cs + k];
            unsigned n = (unsigned)(bn + cs + k);
            ull cand = ((ull)f2ord(v) << 32) | (ull)(0xFFFFFFFFu - n);
            if (cand > best) best = cand;
        }
        ull o = __shfl_xor_sync(0xffffffffu, best, 1);
        if (o > best) best = o;
        if ((tid & 1) == 0) atomicMax(&g_tokpack[t & 1][mg], best);
        if (seq) {
            float* orow = seq + (size_t)mg * (TSTEPS * VOCAB) + (size_t)t * VOCAB;
            #pragma unroll
            for (int k4 = 0; k4 < 8; k4++) {
                int n = bn + cs + k4 * 4;
                if (n + 3 < VOCAB) {
                    *(float4*)&orow[n] = make_float4(
                        ep[m * 68 + cs + k4 * 4],     ep[m * 68 + cs + k4 * 4 + 1],
                        ep[m * 68 + cs + k4 * 4 + 2], ep[m * 68 + cs + k4 * 4 + 3]);
                } else {
                    for (int q = 0; q < 4; q++)
                        if (n + q < VOCAB) orow[n + q] = ep[m * 68 + cs + k4 * 4 + q];
                }
            }
        }
    }
}

// ---------------- final pred ----------------
__global__ void final_pred_kernel(float* __restrict__ pred) {
    int b = threadIdx.x;
    pred[b * TSTEPS + (TSTEPS - 1)] = (float)decode_tok(g_tokpack[(TSTEPS - 1) & 1][b]);
}

// ---------------- launch ----------------
extern "C" void kernel_launch(void* const* d_in, const int* in_sizes, int n_in,
                              void* d_out, int out_size) {
    const float* enc_last = (const float*)d_in[0];
    const float* enc_out  = (const float*)d_in[1];
    const float* emb      = (const float*)d_in[2];
    const float* w1       = (const float*)d_in[3];
    const float* w2       = (const float*)d_in[5];
    const float* w3       = (const float*)d_in[7];
    const float* wv       = (const float*)d_in[9];
    const float* w_ih     = (const float*)d_in[10];
    const float* w_hh     = (const float*)d_in[11];
    const float* b_ih     = (const float*)d_in[12];
    const float* b_hh     = (const float*)d_in[13];
    const float* out_w    = (const float*)d_in[14];
    const float* out_b    = (const float*)d_in[15];

    float* out = (float*)d_out;
    const long long SEQ = (long long)BATCH * TSTEPS * VOCAB;
    const long long PRED = (long long)BATCH * TSTEPS;
    float* seq_ptr = ((long long)out_size >= SEQ) ? out : nullptr;
    float* pred_ptr = ((long long)out_size >= SEQ + PRED) ? (out + SEQ) : nullptr;

    cudaFuncSetAttribute(mma_gemm<1>, cudaFuncAttributeMaxDynamicSharedMemorySize, MM_SMEM);
    cudaFuncSetAttribute(mma_gemm<2>, cudaFuncAttributeMaxDynamicSharedMemorySize, MM_SMEM);

    // precompute (CUDA-core, R4-proven)
    init_hc_kernel<<<BATCH, HID>>>(enc_last);
    matvecT_kernel<<<HID, 256>>>(w3, HID, wv, 0);
    matvecT_kernel<<<HID, 256>>>(w2, HID, nullptr, 1);
    matvecT_kernel<<<HID, 256>>>(w1, WDIM, nullptr, 2);
    attn_ctx_kernel<<<BATCH, 256>>>(enc_out);

    split_kernel<<<NGATE, 256>>>(w_hh, 0);   // Whh3 (perm)
    split_kernel<<<VPAD, 256>>>(out_w, 1);   // Wout3 (pad)

    pre_gemm<0><<<dim3(NGATE / 64, BATCH / 64), 128>>>(
        nullptr, w_ih + WDIM, LSTM_IN, BATCH, HID, b_ih, b_hh);
    pre_gemm<3><<<dim3(NGATE / 64, (VOCAB + 63) / 64), 128>>>(
        emb, w_ih, LSTM_IN, VOCAB, WDIM, nullptr, nullptr);

    // 27 decode steps on mma.sync tensor cores
    for (int t = 0; t < TSTEPS; t++) {
        mma_gemm<1><<<dim3(NGATE / 64, BATCH / 128), 256, MM_SMEM>>>(
            t, nullptr, nullptr, pred_ptr);
        mma_gemm<2><<<dim3(VPAD / 64, BATCH / 128), 256, MM_SMEM>>>(
            t, out_b, seq_ptr, nullptr);
    }
    if (pred_ptr)
        final_pred_kernel<<<1, BATCH>>>(pred_ptr);
}

// round 10
// speedup vs baseline: 1.6211x; 1.4588x over previous
#include <cuda_runtime.h>
#include <cuda_bf16.h>
#include <math.h>
#include <stdint.h>

#define BATCH 512
#define HID   512
#define WDIM  1024
#define VOCAB 4004
#define VPAD  4096
#define TSTEPS 27
#define SLEN  80
#define NGATE 2048
#define LSTM_IN 1536

typedef unsigned long long ull;

// ---------------- device scratch ----------------
__device__ float g_a2[HID];
__device__ float g_a1[HID];
__device__ float g_a0e[HID];
__device__ float g_ctx[BATCH * HID];
__device__ float g_c[BATCH * HID];
__device__ float g_Gbase[BATCH * NGATE];      // permuted cols
__device__ float g_Eproj[VOCAB * NGATE];      // permuted cols
__device__ ull   g_tokpack[2][BATCH];
__device__ __align__(16) __nv_bfloat16 g_h2[2][2][BATCH * HID];
__device__ __align__(16) __nv_bfloat16 g_Whh2[2][NGATE * HID];    // rows gate-permuted
__device__ __align__(16) __nv_bfloat16 g_Wout2[2][VPAD * HID];    // rows >= VOCAB zero
__device__ __align__(16) __nv_bfloat16 g_emb2[2][VPAD * WDIM];    // rows >= VOCAB zero
__device__ __align__(16) __nv_bfloat16 g_Wihw2[2][NGATE * WDIM];  // rows gate-permuted

// ---------------- helpers ----------------
__device__ __forceinline__ ull ffma2(ull a, ull b, ull c) {
    ull d;
    asm("fma.rn.f32x2 %0, %1, %2, %3;" : "=l"(d) : "l"(a), "l"(b), "l"(c));
    return d;
}
__device__ __forceinline__ float2 unpack2(ull v) {
    float2 r;
    asm("mov.b64 {%0, %1}, %2;" : "=f"(r.x), "=f"(r.y) : "l"(v));
    return r;
}
__device__ __forceinline__ unsigned f2ord(float x) {
    unsigned u = __float_as_uint(x);
    return (u & 0x80000000u) ? ~u : (u | 0x80000000u);
}
__device__ __forceinline__ int decode_tok(ull p) {
    return (int)(0xFFFFFFFFu - (unsigned)(p & 0xFFFFFFFFull));
}
__device__ __forceinline__ float sigmoidf_(float x) { return 1.0f / (1.0f + expf(-x)); }
__device__ __forceinline__ int permrow(int n) { return ((n & 3) << 9) | (n >> 2); }
__device__ __forceinline__ void split2(float x, __nv_bfloat16& a, __nv_bfloat16& b) {
    a = __float2bfloat16(x);
    b = __float2bfloat16(x - __bfloat162float(a));
}

#define CP_ASYNC16P(dst, src, sz) \
    asm volatile("cp.async.cg.shared.global [%0], [%1], 16, %2;\n" \
                 :: "r"(dst), "l"(src), "r"(sz))
#define CP_ASYNC16(dst, src) \
    asm volatile("cp.async.cg.shared.global [%0], [%1], 16;\n" :: "r"(dst), "l"(src))
#define CP_COMMIT() asm volatile("cp.async.commit_group;\n")
#define CP_WAIT1()  asm volatile("cp.async.wait_group 1;\n")
#define CP_WAIT0()  asm volatile("cp.async.wait_group 0;\n")

__device__ __forceinline__ void ldm_x4(uint32_t* r, uint32_t addr) {
    asm volatile("ldmatrix.sync.aligned.m8n8.x4.shared.b16 {%0,%1,%2,%3}, [%4];"
        : "=r"(r[0]), "=r"(r[1]), "=r"(r[2]), "=r"(r[3]) : "r"(addr));
}
__device__ __forceinline__ void mma16816(float* d, const uint32_t* a,
                                         uint32_t b0, uint32_t b1) {
    asm volatile("mma.sync.aligned.m16n8k16.row.col.f32.bf16.bf16.f32 "
        "{%0,%1,%2,%3}, {%4,%5,%6,%7}, {%8,%9}, {%0,%1,%2,%3};"
        : "+f"(d[0]), "+f"(d[1]), "+f"(d[2]), "+f"(d[3])
        : "r"(a[0]), "r"(a[1]), "r"(a[2]), "r"(a[3]), "r"(b0), "r"(b1));
}

// smem layout for mma kernels: per stage A 2 splits x (128 x 80B), B 2 x (64 x 80B)
#define STG_SZ   30720u
#define AOFF(st, s) ((uint32_t)((st) * STG_SZ + (s) * 10240u))
#define BOFF(st, s) ((uint32_t)((st) * STG_SZ + 20480u + (s) * 5120u))
#define SB_BIAS  61440u
#define SB_TOK   61696u
#define MM_SMEM  62464u

// ---------------- init ----------------
__global__ void init_hc_kernel(const float* __restrict__ h0) {
    int b = blockIdx.x, u = threadIdx.x;
    __nv_bfloat16 s0, s1;
    split2(h0[b * HID + u], s0, s1);
    g_h2[0][0][b * HID + u] = s0;
    g_h2[0][1][b * HID + u] = s1;
    g_c[b * HID + u] = 0.0f;
    if (u == 0) { g_tokpack[0][b] = 0ull; g_tokpack[1][b] = 0ull; }
}

// which: 0=Whh(perm,HID), 1=Wout(pad,HID), 2=emb(pad,WDIM), 3=Wih_word(perm,WDIM)
__global__ void split_kernel(const float* __restrict__ src, int which) {
    int r = blockIdx.x;
    int cols = (which >= 2) ? WDIM : HID;
    int srcld = (which == 3) ? LSTM_IN : cols;
    for (int k = threadIdx.x; k < cols; k += 256) {
        float x;
        if (which == 0)      x = src[(size_t)permrow(r) * srcld + k];
        else if (which == 1) x = (r < VOCAB) ? src[(size_t)r * srcld + k] : 0.0f;
        else if (which == 2) x = (r < VOCAB) ? src[(size_t)r * srcld + k] : 0.0f;
        else                 x = src[(size_t)permrow(r) * srcld + k];
        __nv_bfloat16 s0, s1;
        split2(x, s0, s1);
        size_t o = (size_t)r * cols + k;
        if (which == 0)      { g_Whh2[0][o] = s0;  g_Whh2[1][o] = s1; }
        else if (which == 1) { g_Wout2[0][o] = s0; g_Wout2[1][o] = s1; }
        else if (which == 2) { g_emb2[0][o] = s0;  g_emb2[1][o] = s1; }
        else                 { g_Wihw2[0][o] = s0; g_Wihw2[1][o] = s1; }
    }
}

// ---------------- a-chain mat-vecs ----------------
__global__ void matvecT_kernel(const float* __restrict__ Mt, int ld,
                               const float* __restrict__ vin_ext, int stage) {
    __shared__ float red[256];
    int j = blockIdx.x;
    const float* vin = (stage == 0) ? vin_ext : (stage == 1 ? g_a2 : g_a1);
    float acc = 0.0f;
    for (int h = threadIdx.x; h < HID; h += 256)
        acc += Mt[(size_t)h * ld + j] * vin[h];
    red[threadIdx.x] = acc;
    __syncthreads();
    for (int s = 128; s > 0; s >>= 1) {
        if (threadIdx.x < s) red[threadIdx.x] += red[threadIdx.x + s];
        __syncthreads();
    }
    if (threadIdx.x == 0) {
        float r = red[0];
        if (stage == 0)      g_a2[j]  = r;
        else if (stage == 1) g_a1[j]  = r;
        else                 g_a0e[j] = r;
    }
}

// ---------------- attention context (step-invariant) ----------------
__global__ void attn_ctx_kernel(const float* __restrict__ enc) {
    __shared__ float sa[HID];
    __shared__ float sE[SLEN];
    __shared__ float sW[SLEN];
    int b = blockIdx.x, tid = threadIdx.x;
    sa[tid] = g_a0e[tid];
    sa[tid + 256] = g_a0e[tid + 256];
    __syncthreads();
    int w = tid >> 5, lane = tid & 31;
    for (int s = w; s < SLEN; s += 8) {
        const float* row = enc + ((size_t)b * SLEN + s) * HID;
        float acc = 0.0f;
        for (int k = lane; k < HID; k += 32) acc += row[k] * sa[k];
        #pragma unroll
        for (int off = 16; off > 0; off >>= 1)
            acc += __shfl_xor_sync(0xffffffffu, acc, off);
        if (lane == 0) sE[s] = acc;
    }
    __syncthreads();
    if (tid < 32) {
        float v0 = (tid < SLEN) ? sE[tid] : -INFINITY;
        float v1 = (tid + 32 < SLEN) ? sE[tid + 32] : -INFINITY;
        float v2 = (tid + 64 < SLEN) ? sE[tid + 64] : -INFINITY;
        float m = fmaxf(v0, fmaxf(v1, v2));
        #pragma unroll
        for (int off = 16; off > 0; off >>= 1)
            m = fmaxf(m, __shfl_xor_sync(0xffffffffu, m, off));
        float e0 = (tid < SLEN) ? expf(v0 - m) : 0.0f;
        float e1 = (tid + 32 < SLEN) ? expf(v1 - m) : 0.0f;
        float e2 = (tid + 64 < SLEN) ? expf(v2 - m) : 0.0f;
        float s = e0 + e1 + e2;
        #pragma unroll
        for (int off = 16; off > 0; off >>= 1)
            s += __shfl_xor_sync(0xffffffffu, s, off);
        if (tid < SLEN)      sW[tid]      = e0 / s;
        if (tid + 32 < SLEN) sW[tid + 32] = e1 / s;
        if (tid + 64 < SLEN) sW[tid + 64] = e2 / s;
    }
    __syncthreads();
    for (int h = tid; h < HID; h += 256) {
        float acc = 0.0f;
        for (int s = 0; s < SLEN; s++)
            acc += sW[s] * enc[((size_t)b * SLEN + s) * HID + h];
        g_ctx[b * HID + h] = acc;
    }
}

// ---------------- FFMA2 Gbase GEMM (R4-proven; small, one-shot) -------------
__global__ __launch_bounds__(128, 4)
void pre_gemm_gbase(const float* __restrict__ Bp,
                    const float* __restrict__ bias1, const float* __restrict__ bias2) {
    __shared__ __align__(16) float As[2][64 * 32];
    __shared__ __align__(16) float Bs[2][64 * 32];

    const int tid = threadIdx.x;
    const int bm = blockIdx.y * 64;
    const int bn = blockIdx.x * 64;
    const int tm = tid >> 3;
    const int tn = tid & 7;

    const uint32_t sA = (uint32_t)__cvta_generic_to_shared(&As[0][0]);
    const uint32_t sB = (uint32_t)__cvta_generic_to_shared(&Bs[0][0]);

    const int ldrow = tid >> 1;
    const int ldcb  = (tid & 1) * 4;
    const int aswz  = (ldrow >> 2) & 7;
    const int bswz  = (ldrow >> 3) & 7;

    const float* a_srcbase = g_ctx + (size_t)(bm + ldrow) * HID + ldcb * 4;
    const float* b_srcbase = Bp + (size_t)permrow(bn + ldrow) * LSTM_IN + ldcb * 4;

    const uint32_t a_dst = sA + ldrow * 128;
    const uint32_t b_dst = sB + ldrow * 128;

    ull acc[4][8];
    #pragma unroll
    for (int i = 0; i < 4; i++)
        #pragma unroll
        for (int j = 0; j < 8; j++) acc[i][j] = 0ull;

    const int nch = HID >> 5;
    {
        #pragma unroll
        for (int jj = 0; jj < 4; jj++) {
            int c = ldcb + jj;
            CP_ASYNC16(a_dst + ((c ^ aswz) << 4), a_srcbase + jj * 4);
            CP_ASYNC16(b_dst + ((c ^ bswz) << 4), b_srcbase + jj * 4);
        }
        CP_COMMIT();
    }
    for (int ch = 0; ch < nch; ch++) {
        if (ch + 1 < nch) {
            int k0 = (ch + 1) << 5;
            uint32_t soff = ((ch + 1) & 1) ? 8192u : 0u;
            #pragma unroll
            for (int jj = 0; jj < 4; jj++) {
                int c = ldcb + jj;
                CP_ASYNC16(a_dst + soff + ((c ^ aswz) << 4), a_srcbase + k0 + jj * 4);
                CP_ASYNC16(b_dst + soff + ((c ^ bswz) << 4), b_srcbase + k0 + jj * 4);
            }
            CP_COMMIT();
            CP_WAIT1();
        } else {
            CP_WAIT0();
        }
        __syncthreads();

        const float* as = As[ch & 1];
        const float* bs = Bs[ch & 1];
        #pragma unroll
        for (int c = 0; c < 8; c++) {
            const int aoff = (c ^ (tm & 7)) << 2;
            const int boff = (c ^ tn) << 2;
            ulonglong2 av0 = *(const ulonglong2*)&as[(tm * 4 + 0) * 32 + aoff];
            ulonglong2 av1 = *(const ulonglong2*)&as[(tm * 4 + 1) * 32 + aoff];
            ulonglong2 av2 = *(const ulonglong2*)&as[(tm * 4 + 2) * 32 + aoff];
            ulonglong2 av3 = *(const ulonglong2*)&as[(tm * 4 + 3) * 32 + aoff];
            #pragma unroll
            for (int j = 0; j < 8; j++) {
                ulonglong2 bv = *(const ulonglong2*)&bs[(tn * 8 + j) * 32 + boff];
                acc[0][j] = ffma2(av0.x, bv.x, acc[0][j]);
                acc[0][j] = ffma2(av0.y, bv.y, acc[0][j]);
                acc[1][j] = ffma2(av1.x, bv.x, acc[1][j]);
                acc[1][j] = ffma2(av1.y, bv.y, acc[1][j]);
                acc[2][j] = ffma2(av2.x, bv.x, acc[2][j]);
                acc[2][j] = ffma2(av2.y, bv.y, acc[2][j]);
                acc[3][j] = ffma2(av3.x, bv.x, acc[3][j]);
                acc[3][j] = ffma2(av3.y, bv.y, acc[3][j]);
            }
        }
        __syncthreads();
    }

    const int ncol = bn + tn * 8;
    float badd[8];
    #pragma unroll
    for (int j = 0; j < 8; j++) {
        int pr = permrow(ncol + j);
        badd[j] = bias1[pr] + bias2[pr];
    }
    #pragma unroll
    for (int i = 0; i < 4; i++) {
        int m = bm + tm * 4 + i;
        float2 p0, p1, p2, p3;
        p0 = unpack2(acc[i][0]); p1 = unpack2(acc[i][1]);
        p2 = unpack2(acc[i][2]); p3 = unpack2(acc[i][3]);
        float4 v0 = make_float4(p0.x + p0.y + badd[0], p1.x + p1.y + badd[1],
                                p2.x + p2.y + badd[2], p3.x + p3.y + badd[3]);
        p0 = unpack2(acc[i][4]); p1 = unpack2(acc[i][5]);
        p2 = unpack2(acc[i][6]); p3 = unpack2(acc[i][7]);
        float4 v1 = make_float4(p0.x + p0.y + badd[4], p1.x + p1.y + badd[5],
                                p2.x + p2.y + badd[6], p3.x + p3.y + badd[7]);
        *reinterpret_cast<float4*>(g_Gbase + (size_t)m * NGATE + ncol)     = v0;
        *reinterpret_cast<float4*>(g_Gbase + (size_t)m * NGATE + ncol + 4) = v1;
    }
}

// ---------------- mma.sync 2-split GEMM, 128x64 tile ------------------------
// MODE 1: gates = h[t] @ Whh^T + Gbase + Eproj[tok]; fused LSTM -> h[t+1], c
// MODE 2: logits = h[t+1] @ Wout^T + out_b; seq store + argmax
// MODE 3: Eproj = emb @ Wih_word^T (one-shot precompute)
template <int MODE>
__global__ __launch_bounds__(256)
void mma_gemm(int t, const float* __restrict__ bias1,
              float* __restrict__ seq, float* __restrict__ pred) {
    extern __shared__ __align__(16) char smem[];
    const uint32_t sbase = (uint32_t)__cvta_generic_to_shared(smem);

    const int tid = threadIdx.x;
    const int wid = tid >> 5;
    const int lane = tid & 31;
    const int bm = blockIdx.y * 128;
    const int bn = blockIdx.x * 64;
    const int wm = (wid & 3) * 32;
    const int wn = (wid >> 2) * 32;

    const int K = (MODE == 3) ? WDIM : HID;
    const __nv_bfloat16* Aps[2];
    const __nv_bfloat16* Bps[2];
    if (MODE == 1) {
        Aps[0] = g_h2[t & 1][0];  Aps[1] = g_h2[t & 1][1];
        Bps[0] = g_Whh2[0];       Bps[1] = g_Whh2[1];
    } else if (MODE == 2) {
        Aps[0] = g_h2[(t + 1) & 1][0]; Aps[1] = g_h2[(t + 1) & 1][1];
        Bps[0] = g_Wout2[0];           Bps[1] = g_Wout2[1];
    } else {
        Aps[0] = g_emb2[0];  Aps[1] = g_emb2[1];
        Bps[0] = g_Wihw2[0]; Bps[1] = g_Wihw2[1];
    }

    int* stok = (int*)(smem + SB_TOK);
    float* sbias = (float*)(smem + SB_BIAS);
    if (MODE == 1 && tid < 128)
        stok[tid] = (t == 0) ? 1 : decode_tok(g_tokpack[(t - 1) & 1][bm + tid]);
    if (MODE == 2) {
        if (blockIdx.x == 0 && tid < 128) g_tokpack[(t + 1) & 1][bm + tid] = 0ull;
        if (tid < 64) {
            int n = bn + tid;
            sbias[tid] = (n < VOCAB) ? bias1[n] : -3e38f;
        }
    }

    float acc[2][4][4];
    #pragma unroll
    for (int i = 0; i < 2; i++)
        #pragma unroll
        for (int j = 0; j < 4; j++)
            #pragma unroll
            for (int k = 0; k < 4; k++) acc[i][j][k] = 0.0f;

    // chunk loader: BK=32, 1536 16B-chunks / 256 threads = 6 each
    auto load_chunk = [&](int ch, int st) {
        const int k0 = ch << 5;
        #pragma unroll
        for (int i = 0; i < 6; i++) {
            int idx = i * 256 + tid;
            uint32_t dst;
            const __nv_bfloat16* src;
            if (idx < 1024) {
                int s = idx >> 9, rem = idx & 511, r = rem >> 2, c = rem & 3;
                dst = sbase + AOFF(st, s) + r * 80 + c * 16;
                src = Aps[s] + (size_t)(bm + r) * K + k0 + c * 8;
            } else {
                int j = idx - 1024;
                int s = j >> 8, rem = j & 255, r = rem >> 2, c = rem & 3;
                dst = sbase + BOFF(st, s) + r * 80 + c * 16;
                src = Bps[s] + (size_t)(bn + r) * K + k0 + c * 8;
            }
            CP_ASYNC16(dst, src);
        }
        CP_COMMIT();
    };

    const int nch = K >> 5;
    load_chunk(0, 0);
    for (int ch = 0; ch < nch; ch++) {
        if (ch + 1 < nch) { load_chunk(ch + 1, (ch + 1) & 1); CP_WAIT1(); }
        else              { CP_WAIT0(); }
        __syncthreads();

        const int st = ch & 1;
        #pragma unroll
        for (int ks = 0; ks < 2; ks++) {
            uint32_t af[2][2][4], bf[2][2][4];
            #pragma unroll
            for (int s = 0; s < 2; s++) {
                #pragma unroll
                for (int mt = 0; mt < 2; mt++)
                    ldm_x4(af[s][mt], sbase + AOFF(st, s) +
                           (wm + mt * 16 + (lane & 15)) * 80 + ks * 32 +
                           ((lane >> 4) << 4));
                #pragma unroll
                for (int g = 0; g < 2; g++)
                    ldm_x4(bf[s][g], sbase + BOFF(st, s) +
                           (wn + g * 16 + (lane & 15)) * 80 + ks * 32 +
                           ((lane >> 4) << 4));
            }
            #pragma unroll
            for (int sa = 0; sa < 2; sa++)
                #pragma unroll
                for (int sb = 0; sb < 2; sb++) {
                    #pragma unroll
                    for (int mt = 0; mt < 2; mt++)
                        #pragma unroll
                        for (int nt = 0; nt < 4; nt++) {
                            int g = nt >> 1, h = nt & 1;
                            mma16816(acc[mt][nt], af[sa][mt],
                                     bf[sb][g][h], bf[sb][g][h + 2]);
                        }
                }
        }
        __syncthreads();
    }

    // accumulators -> smem tile [128][68] f32 (reuses stage buffers)
    float* ep = (float*)smem;
    #pragma unroll
    for (int mt = 0; mt < 2; mt++)
        #pragma unroll
        for (int nt = 0; nt < 4; nt++) {
            int row = wm + mt * 16 + (lane >> 2);
            int col = wn + nt * 8 + (lane & 3) * 2;
            float b0 = 0.0f, b1 = 0.0f;
            if (MODE == 2) { b0 = sbias[col]; b1 = sbias[col + 1]; }
            ep[row * 68 + col]           = acc[mt][nt][0] + b0;
            ep[row * 68 + col + 1]       = acc[mt][nt][1] + b1;
            ep[(row + 8) * 68 + col]     = acc[mt][nt][2] + b0;
            ep[(row + 8) * 68 + col + 1] = acc[mt][nt][3] + b1;
        }
    __syncthreads();

    const int m = tid >> 1;
    const int mg = bm + m;
    if (MODE == 1) {
        const int tok = stok[m];
        const int uo = (tid & 1) * 8;
        const int ho = (t + 1) & 1;
        #pragma unroll
        for (int j = 0; j < 8; j++) {
            int col = (uo + j) * 4;
            int gcol = bn + col;
            int u = gcol >> 2;
            float4 gb = *(const float4*)&g_Gbase[(size_t)mg * NGATE + gcol];
            float4 epj = *(const float4*)&g_Eproj[(size_t)tok * NGATE + gcol];
            float gi = ep[m * 68 + col]     + gb.x + epj.x;
            float gf = ep[m * 68 + col + 1] + gb.y + epj.y;
            float gg = ep[m * 68 + col + 2] + gb.z + epj.z;
            float go = ep[m * 68 + col + 3] + gb.w + epj.w;
            float cn = sigmoidf_(gf) * g_c[mg * HID + u] + sigmoidf_(gi) * tanhf(gg);
            g_c[mg * HID + u] = cn;
            float hn = sigmoidf_(go) * tanhf(cn);
            __nv_bfloat16 s0, s1;
            split2(hn, s0, s1);
            g_h2[ho][0][mg * HID + u] = s0;
            g_h2[ho][1][mg * HID + u] = s1;
        }
        if (blockIdx.x == 0 && (tid & 1) == 0 && t > 0 && pred)
            pred[mg * TSTEPS + (t - 1)] = (float)tok;
    } else if (MODE == 2) {
        const int cs = (tid & 1) * 32;
        ull best = 0ull;
        #pragma unroll
        for (int k = 0; k < 32; k++) {
            float v = ep[m * 68 + cs + k];
            unsigned n = (unsigned)(bn + cs + k);
            ull cand = ((ull)f2ord(v) << 32) | (ull)(0xFFFFFFFFu - n);
            if (cand > best) best = cand;
        }
        ull o = __shfl_xor_sync(0xffffffffu, best, 1);
        if (o > best) best = o;
        if ((tid & 1) == 0) atomicMax(&g_tokpack[t & 1][mg], best);
        if (seq) {
            float* orow = seq + (size_t)mg * (TSTEPS * VOCAB) + (size_t)t * VOCAB;
            #pragma unroll
            for (int k4 = 0; k4 < 8; k4++) {
                int n = bn + cs + k4 * 4;
                if (n + 3 < VOCAB) {
                    *(float4*)&orow[n] = make_float4(
                        ep[m * 68 + cs + k4 * 4],     ep[m * 68 + cs + k4 * 4 + 1],
                        ep[m * 68 + cs + k4 * 4 + 2], ep[m * 68 + cs + k4 * 4 + 3]);
                } else {
                    for (int q = 0; q < 4; q++)
                        if (n + q < VOCAB) orow[n + q] = ep[m * 68 + cs + k4 * 4 + q];
                }
            }
        }
    } else {  // MODE 3: Eproj store
        if (mg < VOCAB) {
            const int cs = (tid & 1) * 32;
            float* orow = g_Eproj + (size_t)mg * NGATE + bn;
            #pragma unroll
            for (int k4 = 0; k4 < 8; k4++)
                *(float4*)&orow[cs + k4 * 4] = make_float4(
                    ep[m * 68 + cs + k4 * 4],     ep[m * 68 + cs + k4 * 4 + 1],
                    ep[m * 68 + cs + k4 * 4 + 2], ep[m * 68 + cs + k4 * 4 + 3]);
        }
    }
}

// ---------------- final pred ----------------
__global__ void final_pred_kernel(float* __restrict__ pred) {
    int b = threadIdx.x;
    pred[b * TSTEPS + (TSTEPS - 1)] = (float)decode_tok(g_tokpack[(TSTEPS - 1) & 1][b]);
}

// ---------------- launch ----------------
extern "C" void kernel_launch(void* const* d_in, const int* in_sizes, int n_in,
                              void* d_out, int out_size) {
    const float* enc_last = (const float*)d_in[0];
    const float* enc_out  = (const float*)d_in[1];
    const float* emb      = (const float*)d_in[2];
    const float* w1       = (const float*)d_in[3];
    const float* w2       = (const float*)d_in[5];
    const float* w3       = (const float*)d_in[7];
    const float* wv       = (const float*)d_in[9];
    const float* w_ih     = (const float*)d_in[10];
    const float* w_hh     = (const float*)d_in[11];
    const float* b_ih     = (const float*)d_in[12];
    const float* b_hh     = (const float*)d_in[13];
    const float* out_w    = (const float*)d_in[14];
    const float* out_b    = (const float*)d_in[15];

    float* out = (float*)d_out;
    const long long SEQ = (long long)BATCH * TSTEPS * VOCAB;
    const long long PRED = (long long)BATCH * TSTEPS;
    float* seq_ptr = ((long long)out_size >= SEQ) ? out : nullptr;
    float* pred_ptr = ((long long)out_size >= SEQ + PRED) ? (out + SEQ) : nullptr;

    cudaFuncSetAttribute(mma_gemm<1>, cudaFuncAttributeMaxDynamicSharedMemorySize, MM_SMEM);
    cudaFuncSetAttribute(mma_gemm<2>, cudaFuncAttributeMaxDynamicSharedMemorySize, MM_SMEM);
    cudaFuncSetAttribute(mma_gemm<3>, cudaFuncAttributeMaxDynamicSharedMemorySize, MM_SMEM);

    // precompute
    init_hc_kernel<<<BATCH, HID>>>(enc_last);
    matvecT_kernel<<<HID, 256>>>(w3, HID, wv, 0);
    matvecT_kernel<<<HID, 256>>>(w2, HID, nullptr, 1);
    matvecT_kernel<<<HID, 256>>>(w1, WDIM, nullptr, 2);
    attn_ctx_kernel<<<BATCH, 256>>>(enc_out);

    split_kernel<<<NGATE, 256>>>(w_hh, 0);   // Whh2 (perm)
    split_kernel<<<VPAD, 256>>>(out_w, 1);   // Wout2 (pad)
    split_kernel<<<VPAD, 256>>>(emb, 2);     // emb2 (pad)
    split_kernel<<<NGATE, 256>>>(w_ih, 3);   // Wihw2 (perm, word cols)

    pre_gemm_gbase<<<dim3(NGATE / 64, BATCH / 64), 128>>>(w_ih + WDIM, b_ih, b_hh);

    // Eproj on tensor cores (one-shot)
    mma_gemm<3><<<dim3(NGATE / 64, VPAD / 128), 256, MM_SMEM>>>(
        0, nullptr, nullptr, nullptr);

    // 27 decode steps on mma.sync tensor cores
    for (int t = 0; t < TSTEPS; t++) {
        mma_gemm<1><<<dim3(NGATE / 64, BATCH / 128), 256, MM_SMEM>>>(
            t, nullptr, nullptr, pred_ptr);
        mma_gemm<2><<<dim3(VPAD / 64, BATCH / 128), 256, MM_SMEM>>>(
            t, out_b, seq_ptr, nullptr);
    }
    if (pred_ptr)
        final_pred_kernel<<<1, BATCH>>>(pred_ptr);
}

// round 13
// speedup vs baseline: 1.8531x; 1.1431x over previous
#include <cuda_runtime.h>
#include <cuda_bf16.h>
#include <math.h>
#include <stdint.h>

#define BATCH 512
#define HID   512
#define WDIM  1024
#define VOCAB 4004
#define VPAD  4096
#define TSTEPS 27
#define SLEN  80
#define NGATE 2048
#define LSTM_IN 1536

typedef unsigned long long ull;

// ---------------- device scratch ----------------
__device__ float g_a2[HID];
__device__ float g_a1[HID];
__device__ float g_a0e[HID];
__device__ float g_ctx[BATCH * HID];
__device__ float g_c[BATCH * HID];
__device__ float g_Gbase[BATCH * NGATE];      // permuted cols
__device__ float g_Eproj[VOCAB * NGATE];      // permuted cols
__device__ ull   g_tokpack[2][BATCH];
__device__ __align__(16) __nv_bfloat16 g_h2[2][2][BATCH * HID];
__device__ __align__(16) __nv_bfloat16 g_Whh2[2][NGATE * HID];    // rows gate-permuted
__device__ __align__(16) __nv_bfloat16 g_Wout2[2][VPAD * HID];    // rows >= VOCAB zero
__device__ __align__(16) __nv_bfloat16 g_emb2[2][VPAD * WDIM];    // rows >= VOCAB zero
__device__ __align__(16) __nv_bfloat16 g_Wihw2[2][NGATE * WDIM];  // rows gate-permuted

// ---------------- helpers ----------------
__device__ __forceinline__ ull ffma2(ull a, ull b, ull c) {
    ull d;
    asm("fma.rn.f32x2 %0, %1, %2, %3;" : "=l"(d) : "l"(a), "l"(b), "l"(c));
    return d;
}
__device__ __forceinline__ float2 unpack2(ull v) {
    float2 r;
    asm("mov.b64 {%0, %1}, %2;" : "=f"(r.x), "=f"(r.y) : "l"(v));
    return r;
}
__device__ __forceinline__ unsigned f2ord(float x) {
    unsigned u = __float_as_uint(x);
    return (u & 0x80000000u) ? ~u : (u | 0x80000000u);
}
__device__ __forceinline__ int decode_tok(ull p) {
    return (int)(0xFFFFFFFFu - (unsigned)(p & 0xFFFFFFFFull));
}
__device__ __forceinline__ float sigmoidf_(float x) { return 1.0f / (1.0f + expf(-x)); }
__device__ __forceinline__ int permrow(int n) { return ((n & 3) << 9) | (n >> 2); }
__device__ __forceinline__ void split2(float x, __nv_bfloat16& a, __nv_bfloat16& b) {
    a = __float2bfloat16(x);
    b = __float2bfloat16(x - __bfloat162float(a));
}

#define CP_ASYNC16(dst, src) \
    asm volatile("cp.async.cg.shared.global [%0], [%1], 16;\n" :: "r"(dst), "l"(src))
#define CP_COMMIT() asm volatile("cp.async.commit_group;\n")
#define CP_WAIT1()  asm volatile("cp.async.wait_group 1;\n")
#define CP_WAIT0()  asm volatile("cp.async.wait_group 0;\n")

__device__ __forceinline__ void ldm_x4(uint32_t* r, uint32_t addr) {
    asm volatile("ldmatrix.sync.aligned.m8n8.x4.shared.b16 {%0,%1,%2,%3}, [%4];"
        : "=r"(r[0]), "=r"(r[1]), "=r"(r[2]), "=r"(r[3]) : "r"(addr));
}
__device__ __forceinline__ void mma16816(float* d, const uint32_t* a,
                                         uint32_t b0, uint32_t b1) {
    asm volatile("mma.sync.aligned.m16n8k16.row.col.f32.bf16.bf16.f32 "
        "{%0,%1,%2,%3}, {%4,%5,%6,%7}, {%8,%9}, {%0,%1,%2,%3};"
        : "+f"(d[0]), "+f"(d[1]), "+f"(d[2]), "+f"(d[3])
        : "r"(a[0]), "r"(a[1]), "r"(a[2]), "r"(a[3]), "r"(b0), "r"(b1));
}

// smem layout for mma kernels: per stage A 2 splits x (128 x 80B), B 2 x (64 x 80B)
#define STG_SZ   30720u
#define AOFF(st, s) ((uint32_t)((st) * STG_SZ + (s) * 10240u))
#define BOFF(st, s) ((uint32_t)((st) * STG_SZ + 20480u + (s) * 5120u))
#define SB_BIAS  61440u
#define SB_TOK   61696u
#define MM_SMEM  62464u

// ---------------- init ----------------
__global__ void init_hc_kernel(const float* __restrict__ h0) {
    int b = blockIdx.x, u = threadIdx.x;
    __nv_bfloat16 s0, s1;
    split2(h0[b * HID + u], s0, s1);
    g_h2[0][0][b * HID + u] = s0;
    g_h2[0][1][b * HID + u] = s1;
    g_c[b * HID + u] = 0.0f;
    if (u == 0) { g_tokpack[0][b] = 0ull; g_tokpack[1][b] = 0ull; }
}

// which: 0=Whh(perm,HID), 1=Wout(pad,HID), 2=emb(pad,WDIM), 3=Wih_word(perm,WDIM)
__global__ void split_kernel(const float* __restrict__ src, int which) {
    int r = blockIdx.x;
    int cols = (which >= 2) ? WDIM : HID;
    int srcld = (which == 3) ? LSTM_IN : cols;
    for (int k = threadIdx.x; k < cols; k += 256) {
        float x;
        if (which == 0)      x = src[(size_t)permrow(r) * srcld + k];
        else if (which == 1) x = (r < VOCAB) ? src[(size_t)r * srcld + k] : 0.0f;
        else if (which == 2) x = (r < VOCAB) ? src[(size_t)r * srcld + k] : 0.0f;
        else                 x = src[(size_t)permrow(r) * srcld + k];
        __nv_bfloat16 s0, s1;
        split2(x, s0, s1);
        size_t o = (size_t)r * cols + k;
        if (which == 0)      { g_Whh2[0][o] = s0;  g_Whh2[1][o] = s1; }
        else if (which == 1) { g_Wout2[0][o] = s0; g_Wout2[1][o] = s1; }
        else if (which == 2) { g_emb2[0][o] = s0;  g_emb2[1][o] = s1; }
        else                 { g_Wihw2[0][o] = s0; g_Wihw2[1][o] = s1; }
    }
}

// ---------------- a-chain mat-vecs ----------------
__global__ void matvecT_kernel(const float* __restrict__ Mt, int ld,
                               const float* __restrict__ vin_ext, int stage) {
    __shared__ float red[256];
    int j = blockIdx.x;
    const float* vin = (stage == 0) ? vin_ext : (stage == 1 ? g_a2 : g_a1);
    float acc = 0.0f;
    for (int h = threadIdx.x; h < HID; h += 256)
        acc += Mt[(size_t)h * ld + j] * vin[h];
    red[threadIdx.x] = acc;
    __syncthreads();
    for (int s = 128; s > 0; s >>= 1) {
        if (threadIdx.x < s) red[threadIdx.x] += red[threadIdx.x + s];
        __syncthreads();
    }
    if (threadIdx.x == 0) {
        float r = red[0];
        if (stage == 0)      g_a2[j]  = r;
        else if (stage == 1) g_a1[j]  = r;
        else                 g_a0e[j] = r;
    }
}

// ---------------- attention context (step-invariant) ----------------
__global__ void attn_ctx_kernel(const float* __restrict__ enc) {
    __shared__ float sa[HID];
    __shared__ float sE[SLEN];
    __shared__ float sW[SLEN];
    int b = blockIdx.x, tid = threadIdx.x;
    sa[tid] = g_a0e[tid];
    sa[tid + 256] = g_a0e[tid + 256];
    __syncthreads();
    int w = tid >> 5, lane = tid & 31;
    for (int s = w; s < SLEN; s += 8) {
        const float* row = enc + ((size_t)b * SLEN + s) * HID;
        float acc = 0.0f;
        for (int k = lane; k < HID; k += 32) acc += row[k] * sa[k];
        #pragma unroll
        for (int off = 16; off > 0; off >>= 1)
            acc += __shfl_xor_sync(0xffffffffu, acc, off);
        if (lane == 0) sE[s] = acc;
    }
    __syncthreads();
    if (tid < 32) {
        float v0 = (tid < SLEN) ? sE[tid] : -INFINITY;
        float v1 = (tid + 32 < SLEN) ? sE[tid + 32] : -INFINITY;
        float v2 = (tid + 64 < SLEN) ? sE[tid + 64] : -INFINITY;
        float m = fmaxf(v0, fmaxf(v1, v2));
        #pragma unroll
        for (int off = 16; off > 0; off >>= 1)
            m = fmaxf(m, __shfl_xor_sync(0xffffffffu, m, off));
        float e0 = (tid < SLEN) ? expf(v0 - m) : 0.0f;
        float e1 = (tid + 32 < SLEN) ? expf(v1 - m) : 0.0f;
        float e2 = (tid + 64 < SLEN) ? expf(v2 - m) : 0.0f;
        float s = e0 + e1 + e2;
        #pragma unroll
        for (int off = 16; off > 0; off >>= 1)
            s += __shfl_xor_sync(0xffffffffu, s, off);
        if (tid < SLEN)      sW[tid]      = e0 / s;
        if (tid + 32 < SLEN) sW[tid + 32] = e1 / s;
        if (tid + 64 < SLEN) sW[tid + 64] = e2 / s;
    }
    __syncthreads();
    for (int h = tid; h < HID; h += 256) {
        float acc = 0.0f;
        for (int s = 0; s < SLEN; s++)
            acc += sW[s] * enc[((size_t)b * SLEN + s) * HID + h];
        g_ctx[b * HID + h] = acc;
    }
}

// ---------------- FFMA2 Gbase GEMM (R4-proven; small, one-shot) -------------
__global__ __launch_bounds__(128, 4)
void pre_gemm_gbase(const float* __restrict__ Bp,
                    const float* __restrict__ bias1, const float* __restrict__ bias2) {
    __shared__ __align__(16) float As[2][64 * 32];
    __shared__ __align__(16) float Bs[2][64 * 32];

    const int tid = threadIdx.x;
    const int bm = blockIdx.y * 64;
    const int bn = blockIdx.x * 64;
    const int tm = tid >> 3;
    const int tn = tid & 7;

    const uint32_t sA = (uint32_t)__cvta_generic_to_shared(&As[0][0]);
    const uint32_t sB = (uint32_t)__cvta_generic_to_shared(&Bs[0][0]);

    const int ldrow = tid >> 1;
    const int ldcb  = (tid & 1) * 4;
    const int aswz  = (ldrow >> 2) & 7;
    const int bswz  = (ldrow >> 3) & 7;

    const float* a_srcbase = g_ctx + (size_t)(bm + ldrow) * HID + ldcb * 4;
    const float* b_srcbase = Bp + (size_t)permrow(bn + ldrow) * LSTM_IN + ldcb * 4;

    const uint32_t a_dst = sA + ldrow * 128;
    const uint32_t b_dst = sB + ldrow * 128;

    ull acc[4][8];
    #pragma unroll
    for (int i = 0; i < 4; i++)
        #pragma unroll
        for (int j = 0; j < 8; j++) acc[i][j] = 0ull;

    const int nch = HID >> 5;
    {
        #pragma unroll
        for (int jj = 0; jj < 4; jj++) {
            int c = ldcb + jj;
            CP_ASYNC16(a_dst + ((c ^ aswz) << 4), a_srcbase + jj * 4);
            CP_ASYNC16(b_dst + ((c ^ bswz) << 4), b_srcbase + jj * 4);
        }
        CP_COMMIT();
    }
    for (int ch = 0; ch < nch; ch++) {
        if (ch + 1 < nch) {
            int k0 = (ch + 1) << 5;
            uint32_t soff = ((ch + 1) & 1) ? 8192u : 0u;
            #pragma unroll
            for (int jj = 0; jj < 4; jj++) {
                int c = ldcb + jj;
                CP_ASYNC16(a_dst + soff + ((c ^ aswz) << 4), a_srcbase + k0 + jj * 4);
                CP_ASYNC16(b_dst + soff + ((c ^ bswz) << 4), b_srcbase + k0 + jj * 4);
            }
            CP_COMMIT();
            CP_WAIT1();
        } else {
            CP_WAIT0();
        }
        __syncthreads();

        const float* as = As[ch & 1];
        const float* bs = Bs[ch & 1];
        #pragma unroll
        for (int c = 0; c < 8; c++) {
            const int aoff = (c ^ (tm & 7)) << 2;
            const int boff = (c ^ tn) << 2;
            ulonglong2 av0 = *(const ulonglong2*)&as[(tm * 4 + 0) * 32 + aoff];
            ulonglong2 av1 = *(const ulonglong2*)&as[(tm * 4 + 1) * 32 + aoff];
            ulonglong2 av2 = *(const ulonglong2*)&as[(tm * 4 + 2) * 32 + aoff];
            ulonglong2 av3 = *(const ulonglong2*)&as[(tm * 4 + 3) * 32 + aoff];
            #pragma unroll
            for (int j = 0; j < 8; j++) {
                ulonglong2 bv = *(const ulonglong2*)&bs[(tn * 8 + j) * 32 + boff];
                acc[0][j] = ffma2(av0.x, bv.x, acc[0][j]);
                acc[0][j] = ffma2(av0.y, bv.y, acc[0][j]);
                acc[1][j] = ffma2(av1.x, bv.x, acc[1][j]);
                acc[1][j] = ffma2(av1.y, bv.y, acc[1][j]);
                acc[2][j] = ffma2(av2.x, bv.x, acc[2][j]);
                acc[2][j] = ffma2(av2.y, bv.y, acc[2][j]);
                acc[3][j] = ffma2(av3.x, bv.x, acc[3][j]);
                acc[3][j] = ffma2(av3.y, bv.y, acc[3][j]);
            }
        }
        __syncthreads();
    }

    const int ncol = bn + tn * 8;
    float badd[8];
    #pragma unroll
    for (int j = 0; j < 8; j++) {
        int pr = permrow(ncol + j);
        badd[j] = bias1[pr] + bias2[pr];
    }
    #pragma unroll
    for (int i = 0; i < 4; i++) {
        int m = bm + tm * 4 + i;
        float2 p0, p1, p2, p3;
        p0 = unpack2(acc[i][0]); p1 = unpack2(acc[i][1]);
        p2 = unpack2(acc[i][2]); p3 = unpack2(acc[i][3]);
        float4 v0 = make_float4(p0.x + p0.y + badd[0], p1.x + p1.y + badd[1],
                                p2.x + p2.y + badd[2], p3.x + p3.y + badd[3]);
        p0 = unpack2(acc[i][4]); p1 = unpack2(acc[i][5]);
        p2 = unpack2(acc[i][6]); p3 = unpack2(acc[i][7]);
        float4 v1 = make_float4(p0.x + p0.y + badd[4], p1.x + p1.y + badd[5],
                                p2.x + p2.y + badd[6], p3.x + p3.y + badd[7]);
        *reinterpret_cast<float4*>(g_Gbase + (size_t)m * NGATE + ncol)     = v0;
        *reinterpret_cast<float4*>(g_Gbase + (size_t)m * NGATE + ncol + 4) = v1;
    }
}

// ---------------- mma.sync 2-split / 3-product GEMM, 128x64 tile ------------
// products enumerated via PA/PB arrays (R9-proven structure):
//   (0,0), (0,1), (1,0); the (1,1) term (~2^-32 relative) is omitted.
// MODE 1: gates = h[t] @ Whh^T + Gbase + Eproj[tok]; fused LSTM -> h[t+1], c
// MODE 2: logits = h[t+1] @ Wout^T + out_b; seq store + argmax
// MODE 3: Eproj = emb @ Wih_word^T (one-shot precompute)
template <int MODE>
__global__ __launch_bounds__(256)
void mma_gemm(int t, const float* __restrict__ bias1,
              float* __restrict__ seq, float* __restrict__ pred) {
    extern __shared__ __align__(16) char smem[];
    const uint32_t sbase = (uint32_t)__cvta_generic_to_shared(smem);

    const int tid = threadIdx.x;
    const int wid = tid >> 5;
    const int lane = tid & 31;
    const int bm = blockIdx.y * 128;
    const int bn = blockIdx.x * 64;
    const int wm = (wid & 3) * 32;
    const int wn = (wid >> 2) * 32;

    const int K = (MODE == 3) ? WDIM : HID;
    const __nv_bfloat16* Aps[2];
    const __nv_bfloat16* Bps[2];
    if (MODE == 1) {
        Aps[0] = g_h2[t & 1][0];  Aps[1] = g_h2[t & 1][1];
        Bps[0] = g_Whh2[0];       Bps[1] = g_Whh2[1];
    } else if (MODE == 2) {
        Aps[0] = g_h2[(t + 1) & 1][0]; Aps[1] = g_h2[(t + 1) & 1][1];
        Bps[0] = g_Wout2[0];           Bps[1] = g_Wout2[1];
    } else {
        Aps[0] = g_emb2[0];  Aps[1] = g_emb2[1];
        Bps[0] = g_Wihw2[0]; Bps[1] = g_Wihw2[1];
    }

    int* stok = (int*)(smem + SB_TOK);
    float* sbias = (float*)(smem + SB_BIAS);
    if (MODE == 1 && tid < 128)
        stok[tid] = (t == 0) ? 1 : decode_tok(g_tokpack[(t - 1) & 1][bm + tid]);
    if (MODE == 2) {
        if (blockIdx.x == 0 && tid < 128) g_tokpack[(t + 1) & 1][bm + tid] = 0ull;
        if (tid < 64) {
            int n = bn + tid;
            sbias[tid] = (n < VOCAB) ? bias1[n] : -3e38f;
        }
    }

    float acc[2][4][4];
    #pragma unroll
    for (int i = 0; i < 2; i++)
        #pragma unroll
        for (int j = 0; j < 4; j++)
            #pragma unroll
            for (int k = 0; k < 4; k++) acc[i][j][k] = 0.0f;

    // chunk loader: BK=32, 1536 16B-chunks / 256 threads = 6 each
    auto load_chunk = [&](int ch, int st) {
        const int k0 = ch << 5;
        #pragma unroll
        for (int i = 0; i < 6; i++) {
            int idx = i * 256 + tid;
            uint32_t dst;
            const __nv_bfloat16* src;
            if (idx < 1024) {
                int s = idx >> 9, rem = idx & 511, r = rem >> 2, c = rem & 3;
                dst = sbase + AOFF(st, s) + r * 80 + c * 16;
                src = Aps[s] + (size_t)(bm + r) * K + k0 + c * 8;
            } else {
                int j = idx - 1024;
                int s = j >> 8, rem = j & 255, r = rem >> 2, c = rem & 3;
                dst = sbase + BOFF(st, s) + r * 80 + c * 16;
                src = Bps[s] + (size_t)(bn + r) * K + k0 + c * 8;
            }
            CP_ASYNC16(dst, src);
        }
        CP_COMMIT();
    };

    const int nch = K >> 5;
    load_chunk(0, 0);
    for (int ch = 0; ch < nch; ch++) {
        if (ch + 1 < nch) { load_chunk(ch + 1, (ch + 1) & 1); CP_WAIT1(); }
        else              { CP_WAIT0(); }
        __syncthreads();

        const int st = ch & 1;
        #pragma unroll
        for (int ks = 0; ks < 2; ks++) {
            uint32_t af[2][2][4], bf[2][2][4];
            #pragma unroll
            for (int s = 0; s < 2; s++) {
                #pragma unroll
                for (int mt = 0; mt < 2; mt++)
                    ldm_x4(af[s][mt], sbase + AOFF(st, s) +
                           (wm + mt * 16 + (lane & 15)) * 80 + ks * 32 +
                           ((lane >> 4) << 4));
                #pragma unroll
                for (int g = 0; g < 2; g++)
                    ldm_x4(bf[s][g], sbase + BOFF(st, s) +
                           (wn + g * 16 + (lane & 15)) * 80 + ks * 32 +
                           ((lane >> 4) << 4));
            }
            const int PA[3] = {0, 0, 1};
            const int PB[3] = {0, 1, 0};
            #pragma unroll
            for (int p = 0; p < 3; p++) {
                #pragma unroll
                for (int mt = 0; mt < 2; mt++)
                    #pragma unroll
                    for (int nt = 0; nt < 4; nt++) {
                        int g = nt >> 1, h = nt & 1;
                        mma16816(acc[mt][nt], af[PA[p]][mt],
                                 bf[PB[p]][g][h], bf[PB[p]][g][h + 2]);
                    }
            }
        }
        __syncthreads();
    }

    // accumulators -> smem tile [128][68] f32 (reuses stage buffers)
    float* ep = (float*)smem;
    #pragma unroll
    for (int mt = 0; mt < 2; mt++)
        #pragma unroll
        for (int nt = 0; nt < 4; nt++) {
            int row = wm + mt * 16 + (lane >> 2);
            int col = wn + nt * 8 + (lane & 3) * 2;
            float b0 = 0.0f, b1 = 0.0f;
            if (MODE == 2) { b0 = sbias[col]; b1 = sbias[col + 1]; }
            ep[row * 68 + col]           = acc[mt][nt][0] + b0;
            ep[row * 68 + col + 1]       = acc[mt][nt][1] + b1;
            ep[(row + 8) * 68 + col]     = acc[mt][nt][2] + b0;
            ep[(row + 8) * 68 + col + 1] = acc[mt][nt][3] + b1;
        }
    __syncthreads();

    const int m = tid >> 1;
    const int mg = bm + m;
    if (MODE == 1) {
        const int tok = stok[m];
        const int uo = (tid & 1) * 8;
        const int ho = (t + 1) & 1;
        #pragma unroll
        for (int j = 0; j < 8; j++) {
            int col = (uo + j) * 4;
            int gcol = bn + col;
            int u = gcol >> 2;
            float4 gb = *(const float4*)&g_Gbase[(size_t)mg * NGATE + gcol];
            float4 epj = *(const float4*)&g_Eproj[(size_t)tok * NGATE + gcol];
            float gi = ep[m * 68 + col]     + gb.x + epj.x;
            float gf = ep[m * 68 + col + 1] + gb.y + epj.y;
            float gg = ep[m * 68 + col + 2] + gb.z + epj.z;
            float go = ep[m * 68 + col + 3] + gb.w + epj.w;
            float cn = sigmoidf_(gf) * g_c[mg * HID + u] + sigmoidf_(gi) * tanhf(gg);
            g_c[mg * HID + u] = cn;
            float hn = sigmoidf_(go) * tanhf(cn);
            __nv_bfloat16 s0, s1;
            split2(hn, s0, s1);
            g_h2[ho][0][mg * HID + u] = s0;
            g_h2[ho][1][mg * HID + u] = s1;
        }
        if (blockIdx.x == 0 && (tid & 1) == 0 && t > 0 && pred)
            pred[mg * TSTEPS + (t - 1)] = (float)tok;
    } else if (MODE == 2) {
        const int cs = (tid & 1) * 32;
        ull best = 0ull;
        #pragma unroll
        for (int k = 0; k < 32; k++) {
            float v = ep[m * 68 + cs + k];
            unsigned n = (unsigned)(bn + cs + k);
            ull cand = ((ull)f2ord(v) << 32) | (ull)(0xFFFFFFFFu - n);
            if (cand > best) best = cand;
        }
        ull o = __shfl_xor_sync(0xffffffffu, best, 1);
        if (o > best) best = o;
        if ((tid & 1) == 0) atomicMax(&g_tokpack[t & 1][mg], best);
        if (seq) {
            float* orow = seq + (size_t)mg * (TSTEPS * VOCAB) + (size_t)t * VOCAB;
            #pragma unroll
            for (int k4 = 0; k4 < 8; k4++) {
                int n = bn + cs + k4 * 4;
                if (n + 3 < VOCAB) {
                    *(float4*)&orow[n] = make_float4(
                        ep[m * 68 + cs + k4 * 4],     ep[m * 68 + cs + k4 * 4 + 1],
                        ep[m * 68 + cs + k4 * 4 + 2], ep[m * 68 + cs + k4 * 4 + 3]);
                } else {
                    for (int q = 0; q < 4; q++)
                        if (n + q < VOCAB) orow[n + q] = ep[m * 68 + cs + k4 * 4 + q];
                }
            }
        }
    } else {  // MODE 3: Eproj store
        if (mg < VOCAB) {
            const int cs = (tid & 1) * 32;
            float* orow = g_Eproj + (size_t)mg * NGATE + bn;
            #pragma unroll
            for (int k4 = 0; k4 < 8; k4++)
                *(float4*)&orow[cs + k4 * 4] = make_float4(
                    ep[m * 68 + cs + k4 * 4],     ep[m * 68 + cs + k4 * 4 + 1],
                    ep[m * 68 + cs + k4 * 4 + 2], ep[m * 68 + cs + k4 * 4 + 3]);
        }
    }
}

// ---------------- final pred ----------------
__global__ void final_pred_kernel(float* __restrict__ pred) {
    int b = threadIdx.x;
    pred[b * TSTEPS + (TSTEPS - 1)] = (float)decode_tok(g_tokpack[(TSTEPS - 1) & 1][b]);
}

// ---------------- launch ----------------
extern "C" void kernel_launch(void* const* d_in, const int* in_sizes, int n_in,
                              void* d_out, int out_size) {
    const float* enc_last = (const float*)d_in[0];
    const float* enc_out  = (const float*)d_in[1];
    const float* emb      = (const float*)d_in[2];
    const float* w1       = (const float*)d_in[3];
    const float* w2       = (const float*)d_in[5];
    const float* w3       = (const float*)d_in[7];
    const float* wv       = (const float*)d_in[9];
    const float* w_ih     = (const float*)d_in[10];
    const float* w_hh     = (const float*)d_in[11];
    const float* b_ih     = (const float*)d_in[12];
    const float* b_hh     = (const float*)d_in[13];
    const float* out_w    = (const float*)d_in[14];
    const float* out_b    = (const float*)d_in[15];

    float* out = (float*)d_out;
    const long long SEQ = (long long)BATCH * TSTEPS * VOCAB;
    const long long PRED = (long long)BATCH * TSTEPS;
    float* seq_ptr = ((long long)out_size >= SEQ) ? out : nullptr;
    float* pred_ptr = ((long long)out_size >= SEQ + PRED) ? (out + SEQ) : nullptr;

    cudaFuncSetAttribute(mma_gemm<1>, cudaFuncAttributeMaxDynamicSharedMemorySize, MM_SMEM);
    cudaFuncSetAttribute(mma_gemm<2>, cudaFuncAttributeMaxDynamicSharedMemorySize, MM_SMEM);
    cudaFuncSetAttribute(mma_gemm<3>, cudaFuncAttributeMaxDynamicSharedMemorySize, MM_SMEM);

    // precompute
    init_hc_kernel<<<BATCH, HID>>>(enc_last);
    matvecT_kernel<<<HID, 256>>>(w3, HID, wv, 0);
    matvecT_kernel<<<HID, 256>>>(w2, HID, nullptr, 1);
    matvecT_kernel<<<HID, 256>>>(w1, WDIM, nullptr, 2);
    attn_ctx_kernel<<<BATCH, 256>>>(enc_out);

    split_kernel<<<NGATE, 256>>>(w_hh, 0);   // Whh2 (perm)
    split_kernel<<<VPAD, 256>>>(out_w, 1);   // Wout2 (pad)
    split_kernel<<<VPAD, 256>>>(emb, 2);     // emb2 (pad)
    split_kernel<<<NGATE, 256>>>(w_ih, 3);   // Wihw2 (perm, word cols)

    pre_gemm_gbase<<<dim3(NGATE / 64, BATCH / 64), 128>>>(w_ih + WDIM, b_ih, b_hh);

    // Eproj on tensor cores (one-shot)
    mma_gemm<3><<<dim3(NGATE / 64, VPAD / 128), 256, MM_SMEM>>>(
        0, nullptr, nullptr, nullptr);

    // 27 decode steps on mma.sync tensor cores
    for (int t = 0; t < TSTEPS; t++) {
        mma_gemm<1><<<dim3(NGATE / 64, BATCH / 128), 256, MM_SMEM>>>(
            t, nullptr, nullptr, pred_ptr);
        mma_gemm<2><<<dim3(VPAD / 64, BATCH / 128), 256, MM_SMEM>>>(
            t, out_b, seq_ptr, nullptr);
    }
    if (pred_ptr)
        final_pred_kernel<<<1, BATCH>>>(pred_ptr);
}